// round 2
// baseline (speedup 1.0000x reference)
#include <cuda_runtime.h>
#include <cuda_bf16.h>
#include <math.h>

#define BB 4
#define SS 2048
#define DD 64
#define NN 2048
#define NTOK (BB*SS)

// -------- static device scratch (no allocations allowed) ----------
__device__ float g_k[NTOK*DD];
__device__ float g_q[NTOK*DD];
__device__ float g_v[NTOK*DD];
__device__ float g_nu[NTOK*DD];
__device__ float g_pw[NTOK*4];
__device__ float g_us[NTOK];
__device__ float g_outpre[NTOK*DD];
__device__ float g_a[NTOK*DD];

__device__ __forceinline__ float gelu_exact(float x){
    return 0.5f*x*(1.0f + erff(x*0.70710678118654752f));
}

// ---------------------------------------------------------------------------
// Kernel 1: fused projection GEMMs. grid (64 row-tiles, 4 segments), 256 thr.
// seg0: k = l2norm(x@Wk); seg1: v = x@Wv; seg2: q = l2norm(x@Wq);
// seg3: us = ((gelu(x@ir_w1 + ir_b1) @ ir_w2) + ir_b2) > 0
// Tile: 128 rows x 64 cols, K=2048 in 16-chunks, double-buffered smem.
// ---------------------------------------------------------------------------
__global__ void __launch_bounds__(256,2) proj_kernel(
    const float* __restrict__ x,
    const float* __restrict__ Wk, const float* __restrict__ Wv,
    const float* __restrict__ Wq, const float* __restrict__ ir_w1,
    const float* __restrict__ ir_b1, const float* __restrict__ ir_w2,
    const float* __restrict__ ir_b2)
{
    __shared__ __align__(16) float As[2][16][132];  // [k][m] (x transposed)
    __shared__ __align__(16) float Bs[2][16][68];   // [k][n]

    const int seg  = blockIdx.y;
    const int row0 = blockIdx.x * 128;
    const float* __restrict__ B = (seg==0)?Wk:(seg==1)?Wv:(seg==2)?Wq:ir_w1;

    const int tid = threadIdx.x;
    const int tr = tid >> 4;   // 0..15 -> rows tr*8 .. tr*8+7
    const int tc = tid & 15;   // 0..15 -> cols tc*4 .. tc*4+3

    float acc[8][4];
    #pragma unroll
    for (int i=0;i<8;i++)
        #pragma unroll
        for (int j=0;j<4;j++) acc[i][j]=0.f;

    float4 ra[2]; float4 rb;

    // preload chunk 0
    {
        #pragma unroll
        for (int j=0;j<2;j++){
            int s = tid*2 + j;
            int m = s >> 2, k4 = s & 3;
            ra[j] = *(const float4*)&x[(long)(row0+m)*NN + k4*4];
        }
        { int kk = tid >> 4, c4 = tid & 15;
          rb = *(const float4*)&B[(long)kk*DD + c4*4]; }
        #pragma unroll
        for (int j=0;j<2;j++){
            int s = tid*2+j; int m = s>>2, k4 = s&3;
            As[0][k4*4+0][m]=ra[j].x; As[0][k4*4+1][m]=ra[j].y;
            As[0][k4*4+2][m]=ra[j].z; As[0][k4*4+3][m]=ra[j].w;
        }
        { int kk=tid>>4, c4=tid&15; *(float4*)&Bs[0][kk][c4*4] = rb; }
    }
    __syncthreads();

    for (int c=0; c<128; c++){
        const int buf = c & 1;
        if (c+1 < 128){
            int k0 = (c+1)*16;
            #pragma unroll
            for (int j=0;j<2;j++){
                int s = tid*2 + j; int m = s>>2, k4 = s&3;
                ra[j] = *(const float4*)&x[(long)(row0+m)*NN + k0 + k4*4];
            }
            int kk = tid>>4, c4 = tid&15;
            rb = *(const float4*)&B[(long)(k0+kk)*DD + c4*4];
        }
        #pragma unroll
        for (int kk=0; kk<16; kk++){
            float4 a0 = *(float4*)&As[buf][kk][tr*8];
            float4 a1 = *(float4*)&As[buf][kk][tr*8+4];
            float4 bb = *(float4*)&Bs[buf][kk][tc*4];
            float am[8] = {a0.x,a0.y,a0.z,a0.w,a1.x,a1.y,a1.z,a1.w};
            float bn[4] = {bb.x,bb.y,bb.z,bb.w};
            #pragma unroll
            for (int i=0;i<8;i++)
                #pragma unroll
                for (int j=0;j<4;j++) acc[i][j] = fmaf(am[i], bn[j], acc[i][j]);
        }
        if (c+1 < 128){
            int nb = (c+1)&1;
            #pragma unroll
            for (int j=0;j<2;j++){
                int s = tid*2+j; int m=s>>2,k4=s&3;
                As[nb][k4*4+0][m]=ra[j].x; As[nb][k4*4+1][m]=ra[j].y;
                As[nb][k4*4+2][m]=ra[j].z; As[nb][k4*4+3][m]=ra[j].w;
            }
            int kk=tid>>4,c4=tid&15;
            *(float4*)&Bs[nb][kk][c4*4]=rb;
        }
        __syncthreads();
    }

    const unsigned FULL = 0xffffffffu;
    if (seg==0 || seg==2){
        float* dst = (seg==0)? g_k : g_q;
        #pragma unroll
        for (int i=0;i<8;i++){
            float s = acc[i][0]*acc[i][0]+acc[i][1]*acc[i][1]
                    + acc[i][2]*acc[i][2]+acc[i][3]*acc[i][3];
            s += __shfl_xor_sync(FULL, s, 1);
            s += __shfl_xor_sync(FULL, s, 2);
            s += __shfl_xor_sync(FULL, s, 4);
            s += __shfl_xor_sync(FULL, s, 8);
            float inv = 1.0f / fmaxf(sqrtf(s), 1e-12f);
            long row = row0 + tr*8 + i;
            *(float4*)&dst[row*DD + tc*4] =
                make_float4(acc[i][0]*inv, acc[i][1]*inv, acc[i][2]*inv, acc[i][3]*inv);
        }
    } else if (seg==1){
        #pragma unroll
        for (int i=0;i<8;i++){
            long row = row0 + tr*8 + i;
            *(float4*)&g_v[row*DD + tc*4] =
                make_float4(acc[i][0],acc[i][1],acc[i][2],acc[i][3]);
        }
    } else {
        float b1v[4], w2v[4];
        #pragma unroll
        for (int j=0;j<4;j++){ b1v[j]=ir_b1[tc*4+j]; w2v[j]=ir_w2[tc*4+j]; }
        float b2 = ir_b2[0];
        #pragma unroll
        for (int i=0;i<8;i++){
            float p = 0.f;
            #pragma unroll
            for (int j=0;j<4;j++) p += gelu_exact(acc[i][j]+b1v[j]) * w2v[j];
            p += __shfl_xor_sync(FULL, p, 1);
            p += __shfl_xor_sync(FULL, p, 2);
            p += __shfl_xor_sync(FULL, p, 4);
            p += __shfl_xor_sync(FULL, p, 8);
            if (tc==0){
                long row = row0 + tr*8 + i;
                // sigmoid(logit) > 0.5  <=>  logit > 0
                g_us[row] = (p + b2) > 0.f ? 1.f : 0.f;
            }
        }
    }
}

// ---------------------------------------------------------------------------
// Kernel 2: pw = softmax(x @ pw_w + pw_b). warp per token; grid 128 x 256 thr.
// ---------------------------------------------------------------------------
__global__ void __launch_bounds__(256) pw_kernel(
    const float* __restrict__ x, const float* __restrict__ pw_w,
    const float* __restrict__ pw_b)
{
    __shared__ __align__(16) float pwT[3][2048];
    const int tid = threadIdx.x;
    for (int idx = tid; idx < 3*2048; idx += 256){
        int i = idx/3, cc = idx - i*3;
        pwT[cc][i] = pw_w[idx];
    }
    __syncthreads();
    const int warp = tid>>5, lane = tid&31;
    const float b0 = pw_b[0], b1 = pw_b[1], b2 = pw_b[2];
    const unsigned FULL = 0xffffffffu;
    for (int it8 = 0; it8 < 8; it8++){
        long tok = (long)blockIdx.x*64 + warp*8 + it8;
        const float* xr = x + tok*NN;
        float a0=0.f,a1=0.f,a2=0.f;
        #pragma unroll
        for (int it=0; it<16; it++){
            int off = it*128 + lane*4;
            float4 xv = *(const float4*)&xr[off];
            float4 w0 = *(const float4*)&pwT[0][off];
            float4 w1 = *(const float4*)&pwT[1][off];
            float4 w2 = *(const float4*)&pwT[2][off];
            a0 += xv.x*w0.x + xv.y*w0.y + xv.z*w0.z + xv.w*w0.w;
            a1 += xv.x*w1.x + xv.y*w1.y + xv.z*w1.z + xv.w*w1.w;
            a2 += xv.x*w2.x + xv.y*w2.y + xv.z*w2.z + xv.w*w2.w;
        }
        #pragma unroll
        for (int d=1; d<32; d<<=1){
            a0 += __shfl_xor_sync(FULL, a0, d);
            a1 += __shfl_xor_sync(FULL, a1, d);
            a2 += __shfl_xor_sync(FULL, a2, d);
        }
        if (lane==0){
            float l0=a0+b0, l1=a1+b1, l2=a2+b2;
            float m = fmaxf(l0, fmaxf(l1,l2));
            float e0=expf(l0-m), e1=expf(l1-m), e2=expf(l2-m);
            float inv = 1.0f/(e0+e1+e2);
            g_pw[tok*4+0]=e0*inv; g_pw[tok*4+1]=e1*inv;
            g_pw[tok*4+2]=e2*inv; g_pw[tok*4+3]=0.f;
        }
    }
}

// ---------------------------------------------------------------------------
// Kernel 3: nu = gelu(v @ nm_w1 + b1) @ nm_w2 + b2. warp per token.
// grid 1024 x 256 thr (8 tokens per block).
// ---------------------------------------------------------------------------
__global__ void __launch_bounds__(256) nu_kernel(
    const float* __restrict__ nm_w1, const float* __restrict__ nm_b1,
    const float* __restrict__ nm_w2, const float* __restrict__ nm_b2)
{
    __shared__ float W1s[64*128];
    __shared__ float hs[8][128];
    __shared__ float vs[8][64];
    const int tid = threadIdx.x;
    for (int i = tid; i < 64*128; i += 256) W1s[i] = nm_w1[i];
    long tok0 = (long)blockIdx.x*8;
    for (int i = tid; i < 8*64; i += 256){
        int t = i>>6, r = i&63;
        vs[t][r] = g_v[(tok0+t)*DD + r];
    }
    __syncthreads();
    const int warp = tid>>5, lane = tid&31;
    #pragma unroll
    for (int ii=0;ii<4;ii++){
        int i = lane + ii*32;
        float a = nm_b1[i];
        #pragma unroll 8
        for (int r=0;r<64;r++) a = fmaf(vs[warp][r], W1s[r*128+i], a);
        hs[warp][i] = gelu_exact(a);
    }
    __syncwarp();
    #pragma unroll
    for (int jj=0;jj<2;jj++){
        int j = lane + jj*32;
        float a = nm_b2[j];
        #pragma unroll 8
        for (int i=0;i<128;i++) a = fmaf(hs[warp][i], __ldg(&nm_w2[i*64+j]), a);
        g_nu[(tok0+warp)*DD + j] = a;
    }
}

// ---------------------------------------------------------------------------
// Kernel 4: sequential scan. 4 blocks (one per batch), 256 threads.
// Thread (c = tid>>2, rg = tid&3) owns rows rg*16..rg*16+15 of column c of
// fast_H and slow_H (registers). out_f = fa*qh + (q.k)*cf identity avoids
// recomputing q.H after the rank-1 update.
// ---------------------------------------------------------------------------
__global__ void __launch_bounds__(256,1) scan_kernel(
    const float* __restrict__ fa_p, const float* __restrict__ sa_p)
{
    __shared__ float s_err[2][8];
    const int batch = blockIdx.x;
    const int tid = threadIdx.x;
    const int c = tid >> 2;
    const int rg = tid & 3;
    const int lane = tid & 31;
    const int warp = tid >> 5;
    const float fa = *fa_p, sa = *sa_p;
    const float ofa = 1.0f - fa, osa = 1.0f - sa;
    const unsigned FULL = 0xffffffffu;
    // surprise gate: sigmoid(err/(1+1e-6)) > 0.7 <=> err > ln(7/3)*(1+1e-6)
    const float ETHR = 0.8472987077f;

    float F[16], S[16];
    #pragma unroll
    for (int i=0;i<16;i++){ F[i]=0.f; S[i]=0.f; }
    float nsv = 0.f;

    const long tb = (long)batch * SS;
    float qv[16], kv[16], vc, nuc, usv, p0, p1, p2;

    // load t = 0
    {
        const long tok = tb;
        #pragma unroll
        for (int j=0;j<4;j++){
            float4 a4 = *(const float4*)&g_q[tok*DD + rg*16 + j*4];
            qv[j*4]=a4.x; qv[j*4+1]=a4.y; qv[j*4+2]=a4.z; qv[j*4+3]=a4.w;
            float4 b4 = *(const float4*)&g_k[tok*DD + rg*16 + j*4];
            kv[j*4]=b4.x; kv[j*4+1]=b4.y; kv[j*4+2]=b4.z; kv[j*4+3]=b4.w;
        }
        vc  = g_v[tok*DD + c];
        nuc = g_nu[tok*DD + c];
        usv = g_us[tok];
        float4 pw4 = *(const float4*)&g_pw[tok*4];
        p0 = pw4.x; p1 = pw4.y; p2 = pw4.z;
    }

    for (int t=0; t<SS; t++){
        // --- matvec partials on pre-update states ---
        float qh=0.f,qs=0.f,kf=0.f,ks=0.f,qk=0.f;
        #pragma unroll
        for (int i=0;i<16;i++){
            qh = fmaf(qv[i], F[i], qh);
            qs = fmaf(qv[i], S[i], qs);
            kf = fmaf(kv[i], F[i], kf);
            ks = fmaf(kv[i], S[i], ks);
            qk = fmaf(qv[i], kv[i], qk);
        }
        qh += __shfl_xor_sync(FULL,qh,1); qh += __shfl_xor_sync(FULL,qh,2);
        qs += __shfl_xor_sync(FULL,qs,1); qs += __shfl_xor_sync(FULL,qs,2);
        kf += __shfl_xor_sync(FULL,kf,1); kf += __shfl_xor_sync(FULL,kf,2);
        ks += __shfl_xor_sync(FULL,ks,1); ks += __shfl_xor_sync(FULL,ks,2);
        qk += __shfl_xor_sync(FULL,qk,1); qk += __shfl_xor_sync(FULL,qk,2);

        // surprise error (cross-column reduction)
        float pred = 0.5f*(qh+qs);
        float dv = vc - pred;
        float e = dv*dv;
        e += __shfl_xor_sync(FULL,e,4);
        e += __shfl_xor_sync(FULL,e,8);
        e += __shfl_xor_sync(FULL,e,16);
        if (lane == 0) s_err[t&1][warp] = e;

        // --- state updates + outputs (independent of err) ---
        float cf = ofa * (vc - kf);
        float cs = osa * usv * (vc - ks);
        #pragma unroll
        for (int i=0;i<16;i++){
            F[i] = fmaf(kv[i], cf, fa*F[i]);
            S[i] = fmaf(kv[i], cs, sa*S[i]);
        }
        float outf = fmaf(qk, cf, fa*qh);
        float outs = fmaf(qk, cs, sa*qs);

        float nuc_c = nuc, pw0=p0, pw1=p1, pw2=p2;

        // --- prefetch next token's operands (hidden behind barrier) ---
        {
            int tn = (t+1 < SS) ? (t+1) : t;
            const long tok = tb + tn;
            #pragma unroll
            for (int j=0;j<4;j++){
                float4 a4 = *(const float4*)&g_q[tok*DD + rg*16 + j*4];
                qv[j*4]=a4.x; qv[j*4+1]=a4.y; qv[j*4+2]=a4.z; qv[j*4+3]=a4.w;
                float4 b4 = *(const float4*)&g_k[tok*DD + rg*16 + j*4];
                kv[j*4]=b4.x; kv[j*4+1]=b4.y; kv[j*4+2]=b4.z; kv[j*4+3]=b4.w;
            }
            vc  = g_v[tok*DD + c];
            nuc = g_nu[tok*DD + c];
            usv = g_us[tok];
            float4 pw4 = *(const float4*)&g_pw[tok*4];
            p0 = pw4.x; p1 = pw4.y; p2 = pw4.z;
        }

        __syncthreads();
        float err = 0.f;
        #pragma unroll
        for (int w=0; w<8; w++) err += s_err[t&1][w];
        float updn = (err > ETHR) ? 0.1f : 0.0f;
        nsv = fmaf(updn, nuc_c - nsv, nsv);

        if (rg == 0){
            float outt = pw0*outf + pw1*outs + pw2*nsv;
            g_outpre[(tb+t)*DD + c] = outt;
        }
    }
}

// ---------------------------------------------------------------------------
// Kernel 5: RMSNorm. warp per row; grid 1024 x 256 thr.
// ---------------------------------------------------------------------------
__global__ void __launch_bounds__(256) rms_kernel(const float* __restrict__ norm_w){
    long row = (long)blockIdx.x*8 + (threadIdx.x>>5);
    int lane = threadIdx.x & 31;
    float x0 = g_outpre[row*DD + lane];
    float x1 = g_outpre[row*DD + 32 + lane];
    float ss = x0*x0 + x1*x1;
    #pragma unroll
    for (int d=1; d<32; d<<=1) ss += __shfl_xor_sync(0xffffffffu, ss, d);
    float inv = rsqrtf(ss*(1.0f/64.0f) + 1e-6f);
    g_a[row*DD + lane]      = x0*inv*norm_w[lane];
    g_a[row*DD + 32 + lane] = x1*inv*norm_w[32+lane];
}

// ---------------------------------------------------------------------------
// Kernel 6: out = g_a[8192,64] @ Wo[64,2048]. 64x64 tiles.
// ---------------------------------------------------------------------------
__global__ void __launch_bounds__(256,2) outgemm_kernel(
    const float* __restrict__ Wo, float* __restrict__ out)
{
    __shared__ __align__(16) float AsT[64][68];  // [k][row]
    __shared__ __align__(16) float Bs[64][68];   // [k][n]
    const int n0   = blockIdx.x*64;
    const int row0 = blockIdx.y*64;
    const int tid  = threadIdx.x;
    #pragma unroll
    for (int l=0;l<4;l++){
        int s = tid + l*256;
        int rr = s>>4, kq = s&15;
        float4 a4 = *(const float4*)&g_a[(long)(row0+rr)*DD + kq*4];
        AsT[kq*4+0][rr]=a4.x; AsT[kq*4+1][rr]=a4.y;
        AsT[kq*4+2][rr]=a4.z; AsT[kq*4+3][rr]=a4.w;
        float4 b4 = *(const float4*)&Wo[(long)rr*NN + n0 + kq*4];
        *(float4*)&Bs[rr][kq*4] = b4;
    }
    __syncthreads();
    const int tr = tid>>4, tc = tid&15;
    float acc[4][4];
    #pragma unroll
    for (int i=0;i<4;i++)
        #pragma unroll
        for (int j=0;j<4;j++) acc[i][j]=0.f;
    #pragma unroll 8
    for (int k=0;k<64;k++){
        float4 a4 = *(const float4*)&AsT[k][tr*4];
        float4 b4 = *(const float4*)&Bs[k][tc*4];
        float am[4]={a4.x,a4.y,a4.z,a4.w}, bn[4]={b4.x,b4.y,b4.z,b4.w};
        #pragma unroll
        for (int i=0;i<4;i++)
            #pragma unroll
            for (int j=0;j<4;j++) acc[i][j]=fmaf(am[i],bn[j],acc[i][j]);
    }
    #pragma unroll
    for (int i=0;i<4;i++){
        *(float4*)&out[(long)(row0+tr*4+i)*NN + n0 + tc*4] =
            make_float4(acc[i][0],acc[i][1],acc[i][2],acc[i][3]);
    }
}

extern "C" void kernel_launch(void* const* d_in, const int* in_sizes, int n_in,
                              void* d_out, int out_size)
{
    const float* x      = (const float*)d_in[0];
    const float* Wk     = (const float*)d_in[1];
    const float* Wv     = (const float*)d_in[2];
    const float* Wq     = (const float*)d_in[3];
    const float* fa     = (const float*)d_in[4];
    const float* sa     = (const float*)d_in[5];
    const float* nm_w1  = (const float*)d_in[6];
    const float* nm_b1  = (const float*)d_in[7];
    const float* nm_w2  = (const float*)d_in[8];
    const float* nm_b2  = (const float*)d_in[9];
    const float* ir_w1  = (const float*)d_in[10];
    const float* ir_b1  = (const float*)d_in[11];
    const float* ir_w2  = (const float*)d_in[12];
    const float* ir_b2  = (const float*)d_in[13];
    const float* pw_w   = (const float*)d_in[14];
    const float* pw_b   = (const float*)d_in[15];
    const float* Wo     = (const float*)d_in[16];
    const float* norm_w = (const float*)d_in[17];
    float* out = (float*)d_out;

    proj_kernel<<<dim3(64,4), 256>>>(x, Wk, Wv, Wq, ir_w1, ir_b1, ir_w2, ir_b2);
    pw_kernel<<<128, 256>>>(x, pw_w, pw_b);
    nu_kernel<<<1024, 256>>>(nm_w1, nm_b1, nm_w2, nm_b2);
    scan_kernel<<<4, 256>>>(fa, sa);
    rms_kernel<<<1024, 256>>>(norm_w);
    outgemm_kernel<<<dim3(32,128), 256>>>(Wo, out);
}

// round 5
// speedup vs baseline: 1.1611x; 1.1611x over previous
#include <cuda_runtime.h>
#include <cuda_bf16.h>
#include <math.h>

#define BB 4
#define SS 2048
#define DD 64
#define NN 2048
#define NTOK (BB*SS)
#define NPAIR (NTOK/2)

// -------- static device scratch (no allocations allowed) ----------
__device__ float g_k[NTOK*DD];
__device__ float g_q[NTOK*DD];
__device__ float g_v[NTOK*DD];
__device__ float g_nu[NTOK*DD];
__device__ float g_pw[NTOK*4];
__device__ float g_us[NTOK];
__device__ float g_outf[NTOK*DD];
__device__ float g_outs[NTOK*DD];
__device__ float g_ec[NTOK*DD];
__device__ float g_dots[NPAIR*4];   // qk0, qk1, k1.k0, q1.k0
__device__ float g_gate[NTOK];
__device__ float g_outpre[NTOK*DD];
__device__ float g_a[NTOK*DD];

__device__ __forceinline__ float gelu_exact(float x){
    return 0.5f*x*(1.0f + erff(x*0.70710678118654752f));
}

// ---------------------------------------------------------------------------
// Kernel 1: fused projection GEMMs. grid (64 row-tiles, 4 segments), 256 thr.
// seg0: k = l2norm(x@Wk); seg1: v = x@Wv; seg2: q = l2norm(x@Wq);
// seg3: us = ((gelu(x@ir_w1 + ir_b1) @ ir_w2) + ir_b2) > 0
// ---------------------------------------------------------------------------
__global__ void __launch_bounds__(256,2) proj_kernel(
    const float* __restrict__ x,
    const float* __restrict__ Wk, const float* __restrict__ Wv,
    const float* __restrict__ Wq, const float* __restrict__ ir_w1,
    const float* __restrict__ ir_b1, const float* __restrict__ ir_w2,
    const float* __restrict__ ir_b2)
{
    __shared__ __align__(16) float As[2][16][132];  // [k][m] (x transposed)
    __shared__ __align__(16) float Bs[2][16][68];   // [k][n]

    const int seg  = blockIdx.y;
    const int row0 = blockIdx.x * 128;
    const float* __restrict__ B = (seg==0)?Wk:(seg==1)?Wv:(seg==2)?Wq:ir_w1;

    const int tid = threadIdx.x;
    const int tr = tid >> 4;
    const int tc = tid & 15;

    float acc[8][4];
    #pragma unroll
    for (int i=0;i<8;i++)
        #pragma unroll
        for (int j=0;j<4;j++) acc[i][j]=0.f;

    float4 ra[2]; float4 rb;

    {
        #pragma unroll
        for (int j=0;j<2;j++){
            int s = tid*2 + j;
            int m = s >> 2, k4 = s & 3;
            ra[j] = *(const float4*)&x[(long)(row0+m)*NN + k4*4];
        }
        { int kk = tid >> 4, c4 = tid & 15;
          rb = *(const float4*)&B[(long)kk*DD + c4*4]; }
        #pragma unroll
        for (int j=0;j<2;j++){
            int s = tid*2+j; int m = s>>2, k4 = s&3;
            As[0][k4*4+0][m]=ra[j].x; As[0][k4*4+1][m]=ra[j].y;
            As[0][k4*4+2][m]=ra[j].z; As[0][k4*4+3][m]=ra[j].w;
        }
        { int kk=tid>>4, c4=tid&15; *(float4*)&Bs[0][kk][c4*4] = rb; }
    }
    __syncthreads();

    for (int c=0; c<128; c++){
        const int buf = c & 1;
        if (c+1 < 128){
            int k0 = (c+1)*16;
            #pragma unroll
            for (int j=0;j<2;j++){
                int s = tid*2 + j; int m = s>>2, k4 = s&3;
                ra[j] = *(const float4*)&x[(long)(row0+m)*NN + k0 + k4*4];
            }
            int kk = tid>>4, c4 = tid&15;
            rb = *(const float4*)&B[(long)(k0+kk)*DD + c4*4];
        }
        #pragma unroll
        for (int kk=0; kk<16; kk++){
            float4 a0 = *(float4*)&As[buf][kk][tr*8];
            float4 a1 = *(float4*)&As[buf][kk][tr*8+4];
            float4 bb = *(float4*)&Bs[buf][kk][tc*4];
            float am[8] = {a0.x,a0.y,a0.z,a0.w,a1.x,a1.y,a1.z,a1.w};
            float bn[4] = {bb.x,bb.y,bb.z,bb.w};
            #pragma unroll
            for (int i=0;i<8;i++)
                #pragma unroll
                for (int j=0;j<4;j++) acc[i][j] = fmaf(am[i], bn[j], acc[i][j]);
        }
        if (c+1 < 128){
            int nb = (c+1)&1;
            #pragma unroll
            for (int j=0;j<2;j++){
                int s = tid*2+j; int m=s>>2,k4=s&3;
                As[nb][k4*4+0][m]=ra[j].x; As[nb][k4*4+1][m]=ra[j].y;
                As[nb][k4*4+2][m]=ra[j].z; As[nb][k4*4+3][m]=ra[j].w;
            }
            int kk=tid>>4,c4=tid&15;
            *(float4*)&Bs[nb][kk][c4*4]=rb;
        }
        __syncthreads();
    }

    const unsigned FULL = 0xffffffffu;
    if (seg==0 || seg==2){
        float* dst = (seg==0)? g_k : g_q;
        #pragma unroll
        for (int i=0;i<8;i++){
            float s = acc[i][0]*acc[i][0]+acc[i][1]*acc[i][1]
                    + acc[i][2]*acc[i][2]+acc[i][3]*acc[i][3];
            s += __shfl_xor_sync(FULL, s, 1);
            s += __shfl_xor_sync(FULL, s, 2);
            s += __shfl_xor_sync(FULL, s, 4);
            s += __shfl_xor_sync(FULL, s, 8);
            float inv = 1.0f / fmaxf(sqrtf(s), 1e-12f);
            long row = row0 + tr*8 + i;
            *(float4*)&dst[row*DD + tc*4] =
                make_float4(acc[i][0]*inv, acc[i][1]*inv, acc[i][2]*inv, acc[i][3]*inv);
        }
    } else if (seg==1){
        #pragma unroll
        for (int i=0;i<8;i++){
            long row = row0 + tr*8 + i;
            *(float4*)&g_v[row*DD + tc*4] =
                make_float4(acc[i][0],acc[i][1],acc[i][2],acc[i][3]);
        }
    } else {
        float b1v[4], w2v[4];
        #pragma unroll
        for (int j=0;j<4;j++){ b1v[j]=ir_b1[tc*4+j]; w2v[j]=ir_w2[tc*4+j]; }
        float b2 = ir_b2[0];
        #pragma unroll
        for (int i=0;i<8;i++){
            float p = 0.f;
            #pragma unroll
            for (int j=0;j<4;j++) p += gelu_exact(acc[i][j]+b1v[j]) * w2v[j];
            p += __shfl_xor_sync(FULL, p, 1);
            p += __shfl_xor_sync(FULL, p, 2);
            p += __shfl_xor_sync(FULL, p, 4);
            p += __shfl_xor_sync(FULL, p, 8);
            if (tc==0){
                long row = row0 + tr*8 + i;
                g_us[row] = (p + b2) > 0.f ? 1.f : 0.f;
            }
        }
    }
}

// ---------------------------------------------------------------------------
// Kernel 2: pw = softmax(x @ pw_w + pw_b). warp per token.
// ---------------------------------------------------------------------------
__global__ void __launch_bounds__(256) pw_kernel(
    const float* __restrict__ x, const float* __restrict__ pw_w,
    const float* __restrict__ pw_b)
{
    __shared__ __align__(16) float pwT[3][2048];
    const int tid = threadIdx.x;
    for (int idx = tid; idx < 3*2048; idx += 256){
        int i = idx/3, cc = idx - i*3;
        pwT[cc][i] = pw_w[idx];
    }
    __syncthreads();
    const int warp = tid>>5, lane = tid&31;
    const float b0 = pw_b[0], b1 = pw_b[1], b2 = pw_b[2];
    const unsigned FULL = 0xffffffffu;
    for (int it8 = 0; it8 < 8; it8++){
        long tok = (long)blockIdx.x*64 + warp*8 + it8;
        const float* xr = x + tok*NN;
        float a0=0.f,a1=0.f,a2=0.f;
        #pragma unroll
        for (int it=0; it<16; it++){
            int off = it*128 + lane*4;
            float4 xv = *(const float4*)&xr[off];
            float4 w0 = *(const float4*)&pwT[0][off];
            float4 w1 = *(const float4*)&pwT[1][off];
            float4 w2 = *(const float4*)&pwT[2][off];
            a0 += xv.x*w0.x + xv.y*w0.y + xv.z*w0.z + xv.w*w0.w;
            a1 += xv.x*w1.x + xv.y*w1.y + xv.z*w1.z + xv.w*w1.w;
            a2 += xv.x*w2.x + xv.y*w2.y + xv.z*w2.z + xv.w*w2.w;
        }
        #pragma unroll
        for (int d=1; d<32; d<<=1){
            a0 += __shfl_xor_sync(FULL, a0, d);
            a1 += __shfl_xor_sync(FULL, a1, d);
            a2 += __shfl_xor_sync(FULL, a2, d);
        }
        if (lane==0){
            float l0=a0+b0, l1=a1+b1, l2=a2+b2;
            float m = fmaxf(l0, fmaxf(l1,l2));
            float e0=expf(l0-m), e1=expf(l1-m), e2=expf(l2-m);
            float inv = 1.0f/(e0+e1+e2);
            g_pw[tok*4+0]=e0*inv; g_pw[tok*4+1]=e1*inv;
            g_pw[tok*4+2]=e2*inv; g_pw[tok*4+3]=0.f;
        }
    }
}

// ---------------------------------------------------------------------------
// Kernel 3: nu = gelu(v @ nm_w1 + b1) @ nm_w2 + b2. warp per token.
// ---------------------------------------------------------------------------
__global__ void __launch_bounds__(256) nu_kernel(
    const float* __restrict__ nm_w1, const float* __restrict__ nm_b1,
    const float* __restrict__ nm_w2, const float* __restrict__ nm_b2)
{
    __shared__ float W1s[64*128];
    __shared__ float hs[8][128];
    __shared__ float vs[8][64];
    const int tid = threadIdx.x;
    for (int i = tid; i < 64*128; i += 256) W1s[i] = nm_w1[i];
    long tok0 = (long)blockIdx.x*8;
    for (int i = tid; i < 8*64; i += 256){
        int t = i>>6, r = i&63;
        vs[t][r] = g_v[(tok0+t)*DD + r];
    }
    __syncthreads();
    const int warp = tid>>5, lane = tid&31;
    #pragma unroll
    for (int ii=0;ii<4;ii++){
        int i = lane + ii*32;
        float a = nm_b1[i];
        #pragma unroll 8
        for (int r=0;r<64;r++) a = fmaf(vs[warp][r], W1s[r*128+i], a);
        hs[warp][i] = gelu_exact(a);
    }
    __syncwarp();
    #pragma unroll
    for (int jj=0;jj<2;jj++){
        int j = lane + jj*32;
        float a = nm_b2[j];
        #pragma unroll 8
        for (int i=0;i<128;i++) a = fmaf(hs[warp][i], __ldg(&nm_w2[i*64+j]), a);
        g_nu[(tok0+warp)*DD + j] = a;
    }
}

// ---------------------------------------------------------------------------
// Kernel 3b: per-pair cross dots. pair p = tokens (2p, 2p+1).
// g_dots[p*4] = { q0.k0, q1.k1, k1.k0, q1.k0 }. warp per pair.
// ---------------------------------------------------------------------------
__global__ void __launch_bounds__(256) dots_kernel(){
    const int tid = threadIdx.x;
    const int warp = tid>>5, lane = tid&31;
    long p = (long)blockIdx.x*8 + warp;
    long t0 = p*2;
    float q0a = g_q[t0*DD+lane],     q0b = g_q[t0*DD+32+lane];
    float k0a = g_k[t0*DD+lane],     k0b = g_k[t0*DD+32+lane];
    float q1a = g_q[(t0+1)*DD+lane], q1b = g_q[(t0+1)*DD+32+lane];
    float k1a = g_k[(t0+1)*DD+lane], k1b = g_k[(t0+1)*DD+32+lane];
    float qk0 = q0a*k0a + q0b*k0b;
    float qk1 = q1a*k1a + q1b*k1b;
    float kk  = k1a*k0a + k1b*k0b;
    float qx  = q1a*k0a + q1b*k0b;
    const unsigned FULL = 0xffffffffu;
    #pragma unroll
    for (int d=1; d<32; d<<=1){
        qk0 += __shfl_xor_sync(FULL,qk0,d);
        qk1 += __shfl_xor_sync(FULL,qk1,d);
        kk  += __shfl_xor_sync(FULL,kk,d);
        qx  += __shfl_xor_sync(FULL,qx,d);
    }
    if (lane==0)
        *(float4*)&g_dots[p*4] = make_float4(qk0,qk1,kk,qx);
}

// ---------------------------------------------------------------------------
// Kernel 4: decoupled H-scan, 2 steps per iteration.
// grid (8,4), 128 threads = 4 independent warps. Each warp handles 2 columns
// (16 threads per column); thread sub=lane&15 owns rows sub*4..sub*4+3 of
// column c of fast/slow H. Emits per-token outf, outs, e_c; no cross-warp
// or cross-column synchronization anywhere.
// ---------------------------------------------------------------------------
__global__ void __launch_bounds__(128,1) scan2_kernel(
    const float* __restrict__ fa_p, const float* __restrict__ sa_p)
{
    const int batch = blockIdx.y;
    const int lane  = threadIdx.x & 31;
    const int warp  = threadIdx.x >> 5;
    const int c     = blockIdx.x*8 + warp*2 + (lane>>4);
    const int sub   = lane & 15;
    const float fa = *fa_p, sa = *sa_p;
    const float ofa = 1.0f - fa, osa = 1.0f - sa;
    const float fa2 = fa*fa, sa2 = sa*sa;
    const unsigned FULL = 0xffffffffu;

    float F[4] = {0,0,0,0}, S[4] = {0,0,0,0};
    const long tb = (long)batch * SS;
    const long pb = (long)batch * (SS/2);

    float4 q0,k0,q1,k1,dts;
    float v0c,v1c,us0,us1;
    {
        long t0 = tb;
        q0 = *(const float4*)&g_q[t0*DD + sub*4];
        k0 = *(const float4*)&g_k[t0*DD + sub*4];
        q1 = *(const float4*)&g_q[(t0+1)*DD + sub*4];
        k1 = *(const float4*)&g_k[(t0+1)*DD + sub*4];
        v0c = g_v[t0*DD + c]; v1c = g_v[(t0+1)*DD + c];
        us0 = g_us[t0];       us1 = g_us[t0+1];
        dts = *(const float4*)&g_dots[pb*4];
    }

    for (int p = 0; p < SS/2; p++){
        const long t0 = tb + p*2;
        float k0a[4] = {k0.x,k0.y,k0.z,k0.w};
        float k1a[4] = {k1.x,k1.y,k1.z,k1.w};
        float q0a[4] = {q0.x,q0.y,q0.z,q0.w};
        float q1a[4] = {q1.x,q1.y,q1.z,q1.w};
        const float qk0 = dts.x, qk1 = dts.y, kk = dts.z, qx = dts.w;
        const float vv0 = v0c, vv1 = v1c;
        const float g0 = osa*us0, g1 = osa*us1;

        // 8 partial dots against pre-update states
        float Df0=0,Df1=0,Qf0=0,Qf1=0,Ds0=0,Ds1=0,Qs0=0,Qs1=0;
        #pragma unroll
        for (int i=0;i<4;i++){
            Df0 = fmaf(k0a[i], F[i], Df0);
            Df1 = fmaf(k1a[i], F[i], Df1);
            Qf0 = fmaf(q0a[i], F[i], Qf0);
            Qf1 = fmaf(q1a[i], F[i], Qf1);
            Ds0 = fmaf(k0a[i], S[i], Ds0);
            Ds1 = fmaf(k1a[i], S[i], Ds1);
            Qs0 = fmaf(q0a[i], S[i], Qs0);
            Qs1 = fmaf(q1a[i], S[i], Qs1);
        }

        // prefetch next pair (latency hidden under the shuffle chain)
        if (p+1 < SS/2){
            long tn = t0 + 2;
            q0 = *(const float4*)&g_q[tn*DD + sub*4];
            k0 = *(const float4*)&g_k[tn*DD + sub*4];
            q1 = *(const float4*)&g_q[(tn+1)*DD + sub*4];
            k1 = *(const float4*)&g_k[(tn+1)*DD + sub*4];
            v0c = g_v[tn*DD + c]; v1c = g_v[(tn+1)*DD + c];
            us0 = g_us[tn];       us1 = g_us[tn+1];
            dts = *(const float4*)&g_dots[(pb+p+1)*4];
        }

        // reduce across the 16 threads of this column
        #pragma unroll
        for (int d=1; d<16; d<<=1){
            Df0 += __shfl_xor_sync(FULL,Df0,d);
            Df1 += __shfl_xor_sync(FULL,Df1,d);
            Qf0 += __shfl_xor_sync(FULL,Qf0,d);
            Qf1 += __shfl_xor_sync(FULL,Qf1,d);
            Ds0 += __shfl_xor_sync(FULL,Ds0,d);
            Ds1 += __shfl_xor_sync(FULL,Ds1,d);
            Qs0 += __shfl_xor_sync(FULL,Qs0,d);
            Qs1 += __shfl_xor_sync(FULL,Qs1,d);
        }

        // step t0 scalars
        float cf0 = ofa * (vv0 - Df0);
        float cs0 = g0  * (vv0 - Ds0);
        float outf0 = fmaf(qk0, cf0, fa*Qf0);
        float outs0 = fmaf(qk0, cs0, sa*Qs0);
        float e0 = vv0 - 0.5f*(Qf0 + Qs0);  e0 = e0*e0;

        // step t0+1 scalars via rank-1 identities
        float kf1 = fmaf(kk, cf0, fa*Df1);
        float ks1 = fmaf(kk, cs0, sa*Ds1);
        float qh1 = fmaf(qx, cf0, fa*Qf1);
        float qs1 = fmaf(qx, cs0, sa*Qs1);
        float cf1 = ofa * (vv1 - kf1);
        float cs1 = g1  * (vv1 - ks1);
        float outf1 = fmaf(qk1, cf1, fa*qh1);
        float outs1 = fmaf(qk1, cs1, sa*qs1);
        float e1 = vv1 - 0.5f*(qh1 + qs1);  e1 = e1*e1;

        // state update: H <- a^2 H + (a*c0)*k0 + c1*k1
        float af = fa*cf0, as = sa*cs0;
        #pragma unroll
        for (int i=0;i<4;i++){
            F[i] = fmaf(k1a[i], cf1, fmaf(k0a[i], af, fa2*F[i]));
            S[i] = fmaf(k1a[i], cs1, fmaf(k0a[i], as, sa2*S[i]));
        }

        if (sub == 0){
            g_outf[t0*DD + c]     = outf0;
            g_outf[(t0+1)*DD + c] = outf1;
            g_outs[t0*DD + c]     = outs0;
            g_outs[(t0+1)*DD + c] = outs1;
            g_ec[t0*DD + c]       = e0;
            g_ec[(t0+1)*DD + c]   = e1;
        }
    }
}

// ---------------------------------------------------------------------------
// Kernel 5: gate = (sum_c e_c > thr) ? 0.1 : 0. warp per token.
// ---------------------------------------------------------------------------
__global__ void __launch_bounds__(256) gate_kernel(){
    const int tid = threadIdx.x;
    const int warp = tid>>5, lane = tid&31;
    long tok = (long)blockIdx.x*8 + warp;
    float s = g_ec[tok*DD + lane] + g_ec[tok*DD + 32 + lane];
    const unsigned FULL = 0xffffffffu;
    #pragma unroll
    for (int d=1; d<32; d<<=1) s += __shfl_xor_sync(FULL,s,d);
    if (lane==0){
        // sigmoid(err/(1+1e-6)) > 0.7  <=>  err > ln(7/3)*(1+1e-6)
        g_gate[tok] = (s > 0.84729871f) ? 0.1f : 0.0f;
    }
}

// ---------------------------------------------------------------------------
// Kernel 6: ns scan + pw combine. 4 blocks x 64 threads (thread = column).
// ---------------------------------------------------------------------------
__global__ void __launch_bounds__(64,1) ns_kernel(){
    const int b = blockIdx.x;
    const int c = threadIdx.x;
    const long tb = (long)b*SS;
    float ns = 0.f;
    for (int t=0; t<SS; t++){
        long tok = tb + t;
        float g  = g_gate[tok];
        float nu = g_nu[tok*DD + c];
        ns = fmaf(g, nu - ns, ns);
        float of = g_outf[tok*DD + c];
        float os = g_outs[tok*DD + c];
        float p0 = g_pw[tok*4+0], p1 = g_pw[tok*4+1], p2 = g_pw[tok*4+2];
        g_outpre[tok*DD + c] = p0*of + p1*os + p2*ns;
    }
}

// ---------------------------------------------------------------------------
// Kernel 7: RMSNorm. warp per row.
// ---------------------------------------------------------------------------
__global__ void __launch_bounds__(256) rms_kernel(const float* __restrict__ norm_w){
    long row = (long)blockIdx.x*8 + (threadIdx.x>>5);
    int lane = threadIdx.x & 31;
    float x0 = g_outpre[row*DD + lane];
    float x1 = g_outpre[row*DD + 32 + lane];
    float ss = x0*x0 + x1*x1;
    #pragma unroll
    for (int d=1; d<32; d<<=1) ss += __shfl_xor_sync(0xffffffffu, ss, d);
    float inv = rsqrtf(ss*(1.0f/64.0f) + 1e-6f);
    g_a[row*DD + lane]      = x0*inv*norm_w[lane];
    g_a[row*DD + 32 + lane] = x1*inv*norm_w[32+lane];
}

// ---------------------------------------------------------------------------
// Kernel 8: out = g_a[8192,64] @ Wo[64,2048]. 64x64 tiles.
// ---------------------------------------------------------------------------
__global__ void __launch_bounds__(256,2) outgemm_kernel(
    const float* __restrict__ Wo, float* __restrict__ out)
{
    __shared__ __align__(16) float AsT[64][68];
    __shared__ __align__(16) float Bs[64][68];
    const int n0   = blockIdx.x*64;
    const int row0 = blockIdx.y*64;
    const int tid  = threadIdx.x;
    #pragma unroll
    for (int l=0;l<4;l++){
        int s = tid + l*256;
        int rr = s>>4, kq = s&15;
        float4 a4 = *(const float4*)&g_a[(long)(row0+rr)*DD + kq*4];
        AsT[kq*4+0][rr]=a4.x; AsT[kq*4+1][rr]=a4.y;
        AsT[kq*4+2][rr]=a4.z; AsT[kq*4+3][rr]=a4.w;
        float4 b4 = *(const float4*)&Wo[(long)rr*NN + n0 + kq*4];
        *(float4*)&Bs[rr][kq*4] = b4;
    }
    __syncthreads();
    const int tr = tid>>4, tc = tid&15;
    float acc[4][4];
    #pragma unroll
    for (int i=0;i<4;i++)
        #pragma unroll
        for (int j=0;j<4;j++) acc[i][j]=0.f;
    #pragma unroll 8
    for (int k=0;k<64;k++){
        float4 a4 = *(const float4*)&AsT[k][tr*4];
        float4 b4 = *(const float4*)&Bs[k][tc*4];
        float am[4]={a4.x,a4.y,a4.z,a4.w}, bn[4]={b4.x,b4.y,b4.z,b4.w};
        #pragma unroll
        for (int i=0;i<4;i++)
            #pragma unroll
            for (int j=0;j<4;j++) acc[i][j]=fmaf(am[i],bn[j],acc[i][j]);
    }
    #pragma unroll
    for (int i=0;i<4;i++){
        *(float4*)&out[(long)(row0+tr*4+i)*NN + n0 + tc*4] =
            make_float4(acc[i][0],acc[i][1],acc[i][2],acc[i][3]);
    }
}

extern "C" void kernel_launch(void* const* d_in, const int* in_sizes, int n_in,
                              void* d_out, int out_size)
{
    const float* x      = (const float*)d_in[0];
    const float* Wk     = (const float*)d_in[1];
    const float* Wv     = (const float*)d_in[2];
    const float* Wq     = (const float*)d_in[3];
    const float* fa     = (const float*)d_in[4];
    const float* sa     = (const float*)d_in[5];
    const float* nm_w1  = (const float*)d_in[6];
    const float* nm_b1  = (const float*)d_in[7];
    const float* nm_w2  = (const float*)d_in[8];
    const float* nm_b2  = (const float*)d_in[9];
    const float* ir_w1  = (const float*)d_in[10];
    const float* ir_b1  = (const float*)d_in[11];
    const float* ir_w2  = (const float*)d_in[12];
    const float* ir_b2  = (const float*)d_in[13];
    const float* pw_w   = (const float*)d_in[14];
    const float* pw_b   = (const float*)d_in[15];
    const float* Wo     = (const float*)d_in[16];
    const float* norm_w = (const float*)d_in[17];
    float* out = (float*)d_out;

    pw_kernel<<<128, 256>>>(x, pw_w, pw_b);
    proj_kernel<<<dim3(64,4), 256>>>(x, Wk, Wv, Wq, ir_w1, ir_b1, ir_w2, ir_b2);
    nu_kernel<<<1024, 256>>>(nm_w1, nm_b1, nm_w2, nm_b2);
    dots_kernel<<<512, 256>>>();
    scan2_kernel<<<dim3(8,4), 128>>>(fa, sa);
    gate_kernel<<<1024, 256>>>();
    ns_kernel<<<4, 64>>>();
    rms_kernel<<<1024, 256>>>(norm_w);
    outgemm_kernel<<<dim3(32,128), 256>>>(Wo, out);
}

// round 6
// speedup vs baseline: 1.7339x; 1.4933x over previous
#include <cuda_runtime.h>
#include <cuda_bf16.h>
#include <math.h>

#define BB 4
#define SS 2048
#define DD 64
#define NN 2048
#define NTOK (BB*SS)
#define NPAIR (NTOK/2)

// -------- static device scratch (no allocations allowed) ----------
__device__ float g_k[NTOK*DD];
__device__ float g_q[NTOK*DD];
__device__ float g_v[NTOK*DD];
__device__ float g_nu[NTOK*DD];
__device__ float g_pw[NTOK*4];
__device__ float g_us[NTOK];
__device__ float g_outf[NTOK*DD];
__device__ float g_outs[NTOK*DD];
__device__ float g_ec[NTOK*DD];
__device__ float g_dots[NPAIR*4];   // qk0, qk1, k1.k0, q1.k0
__device__ float g_gate[NTOK];
__device__ float g_outpre[NTOK*DD];
__device__ float g_a[NTOK*DD];

__device__ __forceinline__ float gelu_exact(float x){
    return 0.5f*x*(1.0f + erff(x*0.70710678118654752f));
}

// ---------------------------------------------------------------------------
// Kernel 1: fused projection GEMMs. grid (64 row-tiles, 4 segments), 256 thr.
// seg0: k = l2norm(x@Wk); seg1: v = x@Wv; seg2: q = l2norm(x@Wq);
// seg3: us = ((gelu(x@ir_w1 + ir_b1) @ ir_w2) + ir_b2) > 0
// ---------------------------------------------------------------------------
__global__ void __launch_bounds__(256,2) proj_kernel(
    const float* __restrict__ x,
    const float* __restrict__ Wk, const float* __restrict__ Wv,
    const float* __restrict__ Wq, const float* __restrict__ ir_w1,
    const float* __restrict__ ir_b1, const float* __restrict__ ir_w2,
    const float* __restrict__ ir_b2)
{
    __shared__ __align__(16) float As[2][16][132];  // [k][m] (x transposed)
    __shared__ __align__(16) float Bs[2][16][68];   // [k][n]

    const int seg  = blockIdx.y;
    const int row0 = blockIdx.x * 128;
    const float* __restrict__ B = (seg==0)?Wk:(seg==1)?Wv:(seg==2)?Wq:ir_w1;

    const int tid = threadIdx.x;
    const int tr = tid >> 4;
    const int tc = tid & 15;

    float acc[8][4];
    #pragma unroll
    for (int i=0;i<8;i++)
        #pragma unroll
        for (int j=0;j<4;j++) acc[i][j]=0.f;

    float4 ra[2]; float4 rb;

    {
        #pragma unroll
        for (int j=0;j<2;j++){
            int s = tid*2 + j;
            int m = s >> 2, k4 = s & 3;
            ra[j] = *(const float4*)&x[(long)(row0+m)*NN + k4*4];
        }
        { int kk = tid >> 4, c4 = tid & 15;
          rb = *(const float4*)&B[(long)kk*DD + c4*4]; }
        #pragma unroll
        for (int j=0;j<2;j++){
            int s = tid*2+j; int m = s>>2, k4 = s&3;
            As[0][k4*4+0][m]=ra[j].x; As[0][k4*4+1][m]=ra[j].y;
            As[0][k4*4+2][m]=ra[j].z; As[0][k4*4+3][m]=ra[j].w;
        }
        { int kk=tid>>4, c4=tid&15; *(float4*)&Bs[0][kk][c4*4] = rb; }
    }
    __syncthreads();

    for (int c=0; c<128; c++){
        const int buf = c & 1;
        if (c+1 < 128){
            int k0 = (c+1)*16;
            #pragma unroll
            for (int j=0;j<2;j++){
                int s = tid*2 + j; int m = s>>2, k4 = s&3;
                ra[j] = *(const float4*)&x[(long)(row0+m)*NN + k0 + k4*4];
            }
            int kk = tid>>4, c4 = tid&15;
            rb = *(const float4*)&B[(long)(k0+kk)*DD + c4*4];
        }
        #pragma unroll
        for (int kk=0; kk<16; kk++){
            float4 a0 = *(float4*)&As[buf][kk][tr*8];
            float4 a1 = *(float4*)&As[buf][kk][tr*8+4];
            float4 bb = *(float4*)&Bs[buf][kk][tc*4];
            float am[8] = {a0.x,a0.y,a0.z,a0.w,a1.x,a1.y,a1.z,a1.w};
            float bn[4] = {bb.x,bb.y,bb.z,bb.w};
            #pragma unroll
            for (int i=0;i<8;i++)
                #pragma unroll
                for (int j=0;j<4;j++) acc[i][j] = fmaf(am[i], bn[j], acc[i][j]);
        }
        if (c+1 < 128){
            int nb = (c+1)&1;
            #pragma unroll
            for (int j=0;j<2;j++){
                int s = tid*2+j; int m=s>>2,k4=s&3;
                As[nb][k4*4+0][m]=ra[j].x; As[nb][k4*4+1][m]=ra[j].y;
                As[nb][k4*4+2][m]=ra[j].z; As[nb][k4*4+3][m]=ra[j].w;
            }
            int kk=tid>>4,c4=tid&15;
            *(float4*)&Bs[nb][kk][c4*4]=rb;
        }
        __syncthreads();
    }

    const unsigned FULL = 0xffffffffu;
    if (seg==0 || seg==2){
        float* dst = (seg==0)? g_k : g_q;
        #pragma unroll
        for (int i=0;i<8;i++){
            float s = acc[i][0]*acc[i][0]+acc[i][1]*acc[i][1]
                    + acc[i][2]*acc[i][2]+acc[i][3]*acc[i][3];
            s += __shfl_xor_sync(FULL, s, 1);
            s += __shfl_xor_sync(FULL, s, 2);
            s += __shfl_xor_sync(FULL, s, 4);
            s += __shfl_xor_sync(FULL, s, 8);
            float inv = 1.0f / fmaxf(sqrtf(s), 1e-12f);
            long row = row0 + tr*8 + i;
            *(float4*)&dst[row*DD + tc*4] =
                make_float4(acc[i][0]*inv, acc[i][1]*inv, acc[i][2]*inv, acc[i][3]*inv);
        }
    } else if (seg==1){
        #pragma unroll
        for (int i=0;i<8;i++){
            long row = row0 + tr*8 + i;
            *(float4*)&g_v[row*DD + tc*4] =
                make_float4(acc[i][0],acc[i][1],acc[i][2],acc[i][3]);
        }
    } else {
        float b1v[4], w2v[4];
        #pragma unroll
        for (int j=0;j<4;j++){ b1v[j]=ir_b1[tc*4+j]; w2v[j]=ir_w2[tc*4+j]; }
        float b2 = ir_b2[0];
        #pragma unroll
        for (int i=0;i<8;i++){
            float p = 0.f;
            #pragma unroll
            for (int j=0;j<4;j++) p += gelu_exact(acc[i][j]+b1v[j]) * w2v[j];
            p += __shfl_xor_sync(FULL, p, 1);
            p += __shfl_xor_sync(FULL, p, 2);
            p += __shfl_xor_sync(FULL, p, 4);
            p += __shfl_xor_sync(FULL, p, 8);
            if (tc==0){
                long row = row0 + tr*8 + i;
                g_us[row] = (p + b2) > 0.f ? 1.f : 0.f;
            }
        }
    }
}

// ---------------------------------------------------------------------------
// Kernel 2: pw = softmax(x @ pw_w + pw_b). warp per token.
// ---------------------------------------------------------------------------
__global__ void __launch_bounds__(256) pw_kernel(
    const float* __restrict__ x, const float* __restrict__ pw_w,
    const float* __restrict__ pw_b)
{
    __shared__ __align__(16) float pwT[3][2048];
    const int tid = threadIdx.x;
    for (int idx = tid; idx < 3*2048; idx += 256){
        int i = idx/3, cc = idx - i*3;
        pwT[cc][i] = pw_w[idx];
    }
    __syncthreads();
    const int warp = tid>>5, lane = tid&31;
    const float b0 = pw_b[0], b1 = pw_b[1], b2 = pw_b[2];
    const unsigned FULL = 0xffffffffu;
    for (int it8 = 0; it8 < 8; it8++){
        long tok = (long)blockIdx.x*64 + warp*8 + it8;
        const float* xr = x + tok*NN;
        float a0=0.f,a1=0.f,a2=0.f;
        #pragma unroll
        for (int it=0; it<16; it++){
            int off = it*128 + lane*4;
            float4 xv = *(const float4*)&xr[off];
            float4 w0 = *(const float4*)&pwT[0][off];
            float4 w1 = *(const float4*)&pwT[1][off];
            float4 w2 = *(const float4*)&pwT[2][off];
            a0 += xv.x*w0.x + xv.y*w0.y + xv.z*w0.z + xv.w*w0.w;
            a1 += xv.x*w1.x + xv.y*w1.y + xv.z*w1.z + xv.w*w1.w;
            a2 += xv.x*w2.x + xv.y*w2.y + xv.z*w2.z + xv.w*w2.w;
        }
        #pragma unroll
        for (int d=1; d<32; d<<=1){
            a0 += __shfl_xor_sync(FULL, a0, d);
            a1 += __shfl_xor_sync(FULL, a1, d);
            a2 += __shfl_xor_sync(FULL, a2, d);
        }
        if (lane==0){
            float l0=a0+b0, l1=a1+b1, l2=a2+b2;
            float m = fmaxf(l0, fmaxf(l1,l2));
            float e0=expf(l0-m), e1=expf(l1-m), e2=expf(l2-m);
            float inv = 1.0f/(e0+e1+e2);
            g_pw[tok*4+0]=e0*inv; g_pw[tok*4+1]=e1*inv;
            g_pw[tok*4+2]=e2*inv; g_pw[tok*4+3]=0.f;
        }
    }
}

// ---------------------------------------------------------------------------
// Kernel 3: nu = gelu(v @ nm_w1 + b1) @ nm_w2 + b2. warp per token.
// ---------------------------------------------------------------------------
__global__ void __launch_bounds__(256) nu_kernel(
    const float* __restrict__ nm_w1, const float* __restrict__ nm_b1,
    const float* __restrict__ nm_w2, const float* __restrict__ nm_b2)
{
    __shared__ float W1s[64*128];
    __shared__ float hs[8][128];
    __shared__ float vs[8][64];
    const int tid = threadIdx.x;
    for (int i = tid; i < 64*128; i += 256) W1s[i] = nm_w1[i];
    long tok0 = (long)blockIdx.x*8;
    for (int i = tid; i < 8*64; i += 256){
        int t = i>>6, r = i&63;
        vs[t][r] = g_v[(tok0+t)*DD + r];
    }
    __syncthreads();
    const int warp = tid>>5, lane = tid&31;
    #pragma unroll
    for (int ii=0;ii<4;ii++){
        int i = lane + ii*32;
        float a = nm_b1[i];
        #pragma unroll 8
        for (int r=0;r<64;r++) a = fmaf(vs[warp][r], W1s[r*128+i], a);
        hs[warp][i] = gelu_exact(a);
    }
    __syncwarp();
    #pragma unroll
    for (int jj=0;jj<2;jj++){
        int j = lane + jj*32;
        float a = nm_b2[j];
        #pragma unroll 8
        for (int i=0;i<128;i++) a = fmaf(hs[warp][i], __ldg(&nm_w2[i*64+j]), a);
        g_nu[(tok0+warp)*DD + j] = a;
    }
}

// ---------------------------------------------------------------------------
// Kernel 3b: per-pair cross dots. pair p = tokens (2p, 2p+1).
// g_dots[p*4] = { q0.k0, q1.k1, k1.k0, q1.k0 }. warp per pair.
// ---------------------------------------------------------------------------
__global__ void __launch_bounds__(256) dots_kernel(){
    const int tid = threadIdx.x;
    const int warp = tid>>5, lane = tid&31;
    long p = (long)blockIdx.x*8 + warp;
    long t0 = p*2;
    float q0a = g_q[t0*DD+lane],     q0b = g_q[t0*DD+32+lane];
    float k0a = g_k[t0*DD+lane],     k0b = g_k[t0*DD+32+lane];
    float q1a = g_q[(t0+1)*DD+lane], q1b = g_q[(t0+1)*DD+32+lane];
    float k1a = g_k[(t0+1)*DD+lane], k1b = g_k[(t0+1)*DD+32+lane];
    float qk0 = q0a*k0a + q0b*k0b;
    float qk1 = q1a*k1a + q1b*k1b;
    float kk  = k1a*k0a + k1b*k0b;
    float qx  = q1a*k0a + q1b*k0b;
    const unsigned FULL = 0xffffffffu;
    #pragma unroll
    for (int d=1; d<32; d<<=1){
        qk0 += __shfl_xor_sync(FULL,qk0,d);
        qk1 += __shfl_xor_sync(FULL,qk1,d);
        kk  += __shfl_xor_sync(FULL,kk,d);
        qx  += __shfl_xor_sync(FULL,qx,d);
    }
    if (lane==0)
        *(float4*)&g_dots[p*4] = make_float4(qk0,qk1,kk,qx);
}

// ---------------------------------------------------------------------------
// Kernel 4: decoupled H-scan, 2 steps per iteration.
// grid (8,4), 128 threads = 4 independent warps. Each warp handles 2 columns
// (16 threads per column); thread sub=lane&15 owns rows sub*4..sub*4+3 of
// column c of fast/slow H. Emits per-token outf, outs, e_c; no cross-warp
// or cross-column synchronization anywhere.
// ---------------------------------------------------------------------------
__global__ void __launch_bounds__(128,1) scan2_kernel(
    const float* __restrict__ fa_p, const float* __restrict__ sa_p)
{
    const int batch = blockIdx.y;
    const int lane  = threadIdx.x & 31;
    const int warp  = threadIdx.x >> 5;
    const int c     = blockIdx.x*8 + warp*2 + (lane>>4);
    const int sub   = lane & 15;
    const float fa = *fa_p, sa = *sa_p;
    const float ofa = 1.0f - fa, osa = 1.0f - sa;
    const float fa2 = fa*fa, sa2 = sa*sa;
    const unsigned FULL = 0xffffffffu;

    float F[4] = {0,0,0,0}, S[4] = {0,0,0,0};
    const long tb = (long)batch * SS;
    const long pb = (long)batch * (SS/2);

    float4 q0,k0,q1,k1,dts;
    float v0c,v1c,us0,us1;
    {
        long t0 = tb;
        q0 = *(const float4*)&g_q[t0*DD + sub*4];
        k0 = *(const float4*)&g_k[t0*DD + sub*4];
        q1 = *(const float4*)&g_q[(t0+1)*DD + sub*4];
        k1 = *(const float4*)&g_k[(t0+1)*DD + sub*4];
        v0c = g_v[t0*DD + c]; v1c = g_v[(t0+1)*DD + c];
        us0 = g_us[t0];       us1 = g_us[t0+1];
        dts = *(const float4*)&g_dots[pb*4];
    }

    for (int p = 0; p < SS/2; p++){
        const long t0 = tb + p*2;
        float k0a[4] = {k0.x,k0.y,k0.z,k0.w};
        float k1a[4] = {k1.x,k1.y,k1.z,k1.w};
        float q0a[4] = {q0.x,q0.y,q0.z,q0.w};
        float q1a[4] = {q1.x,q1.y,q1.z,q1.w};
        const float qk0 = dts.x, qk1 = dts.y, kk = dts.z, qx = dts.w;
        const float vv0 = v0c, vv1 = v1c;
        const float g0 = osa*us0, g1 = osa*us1;

        // 8 partial dots against pre-update states
        float Df0=0,Df1=0,Qf0=0,Qf1=0,Ds0=0,Ds1=0,Qs0=0,Qs1=0;
        #pragma unroll
        for (int i=0;i<4;i++){
            Df0 = fmaf(k0a[i], F[i], Df0);
            Df1 = fmaf(k1a[i], F[i], Df1);
            Qf0 = fmaf(q0a[i], F[i], Qf0);
            Qf1 = fmaf(q1a[i], F[i], Qf1);
            Ds0 = fmaf(k0a[i], S[i], Ds0);
            Ds1 = fmaf(k1a[i], S[i], Ds1);
            Qs0 = fmaf(q0a[i], S[i], Qs0);
            Qs1 = fmaf(q1a[i], S[i], Qs1);
        }

        // prefetch next pair (latency hidden under the shuffle chain)
        if (p+1 < SS/2){
            long tn = t0 + 2;
            q0 = *(const float4*)&g_q[tn*DD + sub*4];
            k0 = *(const float4*)&g_k[tn*DD + sub*4];
            q1 = *(const float4*)&g_q[(tn+1)*DD + sub*4];
            k1 = *(const float4*)&g_k[(tn+1)*DD + sub*4];
            v0c = g_v[tn*DD + c]; v1c = g_v[(tn+1)*DD + c];
            us0 = g_us[tn];       us1 = g_us[tn+1];
            dts = *(const float4*)&g_dots[(pb+p+1)*4];
        }

        // reduce across the 16 threads of this column
        #pragma unroll
        for (int d=1; d<16; d<<=1){
            Df0 += __shfl_xor_sync(FULL,Df0,d);
            Df1 += __shfl_xor_sync(FULL,Df1,d);
            Qf0 += __shfl_xor_sync(FULL,Qf0,d);
            Qf1 += __shfl_xor_sync(FULL,Qf1,d);
            Ds0 += __shfl_xor_sync(FULL,Ds0,d);
            Ds1 += __shfl_xor_sync(FULL,Ds1,d);
            Qs0 += __shfl_xor_sync(FULL,Qs0,d);
            Qs1 += __shfl_xor_sync(FULL,Qs1,d);
        }

        // step t0 scalars
        float cf0 = ofa * (vv0 - Df0);
        float cs0 = g0  * (vv0 - Ds0);
        float outf0 = fmaf(qk0, cf0, fa*Qf0);
        float outs0 = fmaf(qk0, cs0, sa*Qs0);
        float e0 = vv0 - 0.5f*(Qf0 + Qs0);  e0 = e0*e0;

        // step t0+1 scalars via rank-1 identities
        float kf1 = fmaf(kk, cf0, fa*Df1);
        float ks1 = fmaf(kk, cs0, sa*Ds1);
        float qh1 = fmaf(qx, cf0, fa*Qf1);
        float qs1 = fmaf(qx, cs0, sa*Qs1);
        float cf1 = ofa * (vv1 - kf1);
        float cs1 = g1  * (vv1 - ks1);
        float outf1 = fmaf(qk1, cf1, fa*qh1);
        float outs1 = fmaf(qk1, cs1, sa*qs1);
        float e1 = vv1 - 0.5f*(qh1 + qs1);  e1 = e1*e1;

        // state update: H <- a^2 H + (a*c0)*k0 + c1*k1
        float af = fa*cf0, as = sa*cs0;
        #pragma unroll
        for (int i=0;i<4;i++){
            F[i] = fmaf(k1a[i], cf1, fmaf(k0a[i], af, fa2*F[i]));
            S[i] = fmaf(k1a[i], cs1, fmaf(k0a[i], as, sa2*S[i]));
        }

        if (sub == 0){
            g_outf[t0*DD + c]     = outf0;
            g_outf[(t0+1)*DD + c] = outf1;
            g_outs[t0*DD + c]     = outs0;
            g_outs[(t0+1)*DD + c] = outs1;
            g_ec[t0*DD + c]       = e0;
            g_ec[(t0+1)*DD + c]   = e1;
        }
    }
}

// ---------------------------------------------------------------------------
// Kernel 5: gate = (sum_c e_c > thr) ? 0.1 : 0. warp per token.
// ---------------------------------------------------------------------------
__global__ void __launch_bounds__(256) gate_kernel(){
    const int tid = threadIdx.x;
    const int warp = tid>>5, lane = tid&31;
    long tok = (long)blockIdx.x*8 + warp;
    float s = g_ec[tok*DD + lane] + g_ec[tok*DD + 32 + lane];
    const unsigned FULL = 0xffffffffu;
    #pragma unroll
    for (int d=1; d<32; d<<=1) s += __shfl_xor_sync(FULL,s,d);
    if (lane==0){
        // sigmoid(err/(1+1e-6)) > 0.7  <=>  err > ln(7/3)*(1+1e-6)
        g_gate[tok] = (s > 0.84729871f) ? 0.1f : 0.0f;
    }
}

// ---------------------------------------------------------------------------
// Kernel 6: ns scan + pw combine. 4 blocks x 64 threads (thread = column).
// Unroll-8 with batched register prefetch: ~40 independent LDGs in flight
// per group, then 8 dependent FMAs — MLP-bound instead of latency-bound.
// ---------------------------------------------------------------------------
__global__ void __launch_bounds__(64,1) ns_kernel(){
    const int b = blockIdx.x;
    const int c = threadIdx.x;
    const long tb = (long)b*SS;
    float ns = 0.f;
    for (int tt=0; tt<SS; tt+=8){
        float gg[8], nn[8], of[8], os[8];
        float4 pw4[8];
        #pragma unroll
        for (int j=0;j<8;j++){
            long tok = tb + tt + j;
            gg[j] = g_gate[tok];
            nn[j] = g_nu[tok*DD + c];
            of[j] = g_outf[tok*DD + c];
            os[j] = g_outs[tok*DD + c];
            pw4[j] = *(const float4*)&g_pw[tok*4];
        }
        #pragma unroll
        for (int j=0;j<8;j++){
            ns = fmaf(gg[j], nn[j] - ns, ns);
            g_outpre[(tb+tt+j)*DD + c] =
                pw4[j].x*of[j] + pw4[j].y*os[j] + pw4[j].z*ns;
        }
    }
}

// ---------------------------------------------------------------------------
// Kernel 7: RMSNorm. warp per row.
// ---------------------------------------------------------------------------
__global__ void __launch_bounds__(256) rms_kernel(const float* __restrict__ norm_w){
    long row = (long)blockIdx.x*8 + (threadIdx.x>>5);
    int lane = threadIdx.x & 31;
    float x0 = g_outpre[row*DD + lane];
    float x1 = g_outpre[row*DD + 32 + lane];
    float ss = x0*x0 + x1*x1;
    #pragma unroll
    for (int d=1; d<32; d<<=1) ss += __shfl_xor_sync(0xffffffffu, ss, d);
    float inv = rsqrtf(ss*(1.0f/64.0f) + 1e-6f);
    g_a[row*DD + lane]      = x0*inv*norm_w[lane];
    g_a[row*DD + 32 + lane] = x1*inv*norm_w[32+lane];
}

// ---------------------------------------------------------------------------
// Kernel 8: out = g_a[8192,64] @ Wo[64,2048]. 64x64 tiles.
// ---------------------------------------------------------------------------
__global__ void __launch_bounds__(256,2) outgemm_kernel(
    const float* __restrict__ Wo, float* __restrict__ out)
{
    __shared__ __align__(16) float AsT[64][68];
    __shared__ __align__(16) float Bs[64][68];
    const int n0   = blockIdx.x*64;
    const int row0 = blockIdx.y*64;
    const int tid  = threadIdx.x;
    #pragma unroll
    for (int l=0;l<4;l++){
        int s = tid + l*256;
        int rr = s>>4, kq = s&15;
        float4 a4 = *(const float4*)&g_a[(long)(row0+rr)*DD + kq*4];
        AsT[kq*4+0][rr]=a4.x; AsT[kq*4+1][rr]=a4.y;
        AsT[kq*4+2][rr]=a4.z; AsT[kq*4+3][rr]=a4.w;
        float4 b4 = *(const float4*)&Wo[(long)rr*NN + n0 + kq*4];
        *(float4*)&Bs[rr][kq*4] = b4;
    }
    __syncthreads();
    const int tr = tid>>4, tc = tid&15;
    float acc[4][4];
    #pragma unroll
    for (int i=0;i<4;i++)
        #pragma unroll
        for (int j=0;j<4;j++) acc[i][j]=0.f;
    #pragma unroll 8
    for (int k=0;k<64;k++){
        float4 a4 = *(const float4*)&AsT[k][tr*4];
        float4 b4 = *(const float4*)&Bs[k][tc*4];
        float am[4]={a4.x,a4.y,a4.z,a4.w}, bn[4]={b4.x,b4.y,b4.z,b4.w};
        #pragma unroll
        for (int i=0;i<4;i++)
            #pragma unroll
            for (int j=0;j<4;j++) acc[i][j]=fmaf(am[i],bn[j],acc[i][j]);
    }
    #pragma unroll
    for (int i=0;i<4;i++){
        *(float4*)&out[(long)(row0+tr*4+i)*NN + n0 + tc*4] =
            make_float4(acc[i][0],acc[i][1],acc[i][2],acc[i][3]);
    }
}

extern "C" void kernel_launch(void* const* d_in, const int* in_sizes, int n_in,
                              void* d_out, int out_size)
{
    const float* x      = (const float*)d_in[0];
    const float* Wk     = (const float*)d_in[1];
    const float* Wv     = (const float*)d_in[2];
    const float* Wq     = (const float*)d_in[3];
    const float* fa     = (const float*)d_in[4];
    const float* sa     = (const float*)d_in[5];
    const float* nm_w1  = (const float*)d_in[6];
    const float* nm_b1  = (const float*)d_in[7];
    const float* nm_w2  = (const float*)d_in[8];
    const float* nm_b2  = (const float*)d_in[9];
    const float* ir_w1  = (const float*)d_in[10];
    const float* ir_b1  = (const float*)d_in[11];
    const float* ir_w2  = (const float*)d_in[12];
    const float* ir_b2  = (const float*)d_in[13];
    const float* pw_w   = (const float*)d_in[14];
    const float* pw_b   = (const float*)d_in[15];
    const float* Wo     = (const float*)d_in[16];
    const float* norm_w = (const float*)d_in[17];
    float* out = (float*)d_out;

    // Launch order chosen so scan2_kernel sits at profiled position 3.
    pw_kernel<<<128, 256>>>(x, pw_w, pw_b);
    proj_kernel<<<dim3(64,4), 256>>>(x, Wk, Wv, Wq, ir_w1, ir_b1, ir_w2, ir_b2);
    dots_kernel<<<512, 256>>>();
    scan2_kernel<<<dim3(8,4), 128>>>(fa, sa);
    nu_kernel<<<1024, 256>>>(nm_w1, nm_b1, nm_w2, nm_b2);
    gate_kernel<<<1024, 256>>>();
    ns_kernel<<<4, 64>>>();
    rms_kernel<<<1024, 256>>>(norm_w);
    outgemm_kernel<<<dim3(32,128), 256>>>(Wo, out);
}

// round 7
// speedup vs baseline: 1.9680x; 1.1350x over previous
#include <cuda_runtime.h>
#include <cuda_bf16.h>
#include <math.h>

#define BB 4
#define SS 2048
#define DD 64
#define NN 2048
#define NTOK (BB*SS)
#define NQUAD (NTOK/4)

// -------- static device scratch (no allocations allowed) ----------
__device__ float g_k[NTOK*DD];
__device__ float g_q[NTOK*DD];
__device__ float g_v[NTOK*DD];
__device__ float g_nu[NTOK*DD];
__device__ float g_pw[NTOK*4];
__device__ float g_us[NTOK];
__device__ float g_outf[NTOK*DD];
__device__ float g_outs[NTOK*DD];
__device__ float g_ec[NTOK*DD];
__device__ float g_dots[NQUAD*16];  // per quad: qk0..3, kk10,kk20,kk21,kk30,kk31,kk32, qx10,qx20,qx21,qx30,qx31,qx32
__device__ float g_gate[NTOK];
__device__ float g_outpre[NTOK*DD];
__device__ float g_a[NTOK*DD];

__device__ __forceinline__ float gelu_exact(float x){
    return 0.5f*x*(1.0f + erff(x*0.70710678118654752f));
}

// ---------------------------------------------------------------------------
// Kernel 1: fused projection GEMMs. grid (64 row-tiles, 4 segments), 256 thr.
// ---------------------------------------------------------------------------
__global__ void __launch_bounds__(256,2) proj_kernel(
    const float* __restrict__ x,
    const float* __restrict__ Wk, const float* __restrict__ Wv,
    const float* __restrict__ Wq, const float* __restrict__ ir_w1,
    const float* __restrict__ ir_b1, const float* __restrict__ ir_w2,
    const float* __restrict__ ir_b2)
{
    __shared__ __align__(16) float As[2][16][132];
    __shared__ __align__(16) float Bs[2][16][68];

    const int seg  = blockIdx.y;
    const int row0 = blockIdx.x * 128;
    const float* __restrict__ B = (seg==0)?Wk:(seg==1)?Wv:(seg==2)?Wq:ir_w1;

    const int tid = threadIdx.x;
    const int tr = tid >> 4;
    const int tc = tid & 15;

    float acc[8][4];
    #pragma unroll
    for (int i=0;i<8;i++)
        #pragma unroll
        for (int j=0;j<4;j++) acc[i][j]=0.f;

    float4 ra[2]; float4 rb;

    {
        #pragma unroll
        for (int j=0;j<2;j++){
            int s = tid*2 + j;
            int m = s >> 2, k4 = s & 3;
            ra[j] = *(const float4*)&x[(long)(row0+m)*NN + k4*4];
        }
        { int kk = tid >> 4, c4 = tid & 15;
          rb = *(const float4*)&B[(long)kk*DD + c4*4]; }
        #pragma unroll
        for (int j=0;j<2;j++){
            int s = tid*2+j; int m = s>>2, k4 = s&3;
            As[0][k4*4+0][m]=ra[j].x; As[0][k4*4+1][m]=ra[j].y;
            As[0][k4*4+2][m]=ra[j].z; As[0][k4*4+3][m]=ra[j].w;
        }
        { int kk=tid>>4, c4=tid&15; *(float4*)&Bs[0][kk][c4*4] = rb; }
    }
    __syncthreads();

    for (int c=0; c<128; c++){
        const int buf = c & 1;
        if (c+1 < 128){
            int k0 = (c+1)*16;
            #pragma unroll
            for (int j=0;j<2;j++){
                int s = tid*2 + j; int m = s>>2, k4 = s&3;
                ra[j] = *(const float4*)&x[(long)(row0+m)*NN + k0 + k4*4];
            }
            int kk = tid>>4, c4 = tid&15;
            rb = *(const float4*)&B[(long)(k0+kk)*DD + c4*4];
        }
        #pragma unroll
        for (int kk=0; kk<16; kk++){
            float4 a0 = *(float4*)&As[buf][kk][tr*8];
            float4 a1 = *(float4*)&As[buf][kk][tr*8+4];
            float4 bb = *(float4*)&Bs[buf][kk][tc*4];
            float am[8] = {a0.x,a0.y,a0.z,a0.w,a1.x,a1.y,a1.z,a1.w};
            float bn[4] = {bb.x,bb.y,bb.z,bb.w};
            #pragma unroll
            for (int i=0;i<8;i++)
                #pragma unroll
                for (int j=0;j<4;j++) acc[i][j] = fmaf(am[i], bn[j], acc[i][j]);
        }
        if (c+1 < 128){
            int nb = (c+1)&1;
            #pragma unroll
            for (int j=0;j<2;j++){
                int s = tid*2+j; int m=s>>2,k4=s&3;
                As[nb][k4*4+0][m]=ra[j].x; As[nb][k4*4+1][m]=ra[j].y;
                As[nb][k4*4+2][m]=ra[j].z; As[nb][k4*4+3][m]=ra[j].w;
            }
            int kk=tid>>4,c4=tid&15;
            *(float4*)&Bs[nb][kk][c4*4]=rb;
        }
        __syncthreads();
    }

    const unsigned FULL = 0xffffffffu;
    if (seg==0 || seg==2){
        float* dst = (seg==0)? g_k : g_q;
        #pragma unroll
        for (int i=0;i<8;i++){
            float s = acc[i][0]*acc[i][0]+acc[i][1]*acc[i][1]
                    + acc[i][2]*acc[i][2]+acc[i][3]*acc[i][3];
            s += __shfl_xor_sync(FULL, s, 1);
            s += __shfl_xor_sync(FULL, s, 2);
            s += __shfl_xor_sync(FULL, s, 4);
            s += __shfl_xor_sync(FULL, s, 8);
            float inv = 1.0f / fmaxf(sqrtf(s), 1e-12f);
            long row = row0 + tr*8 + i;
            *(float4*)&dst[row*DD + tc*4] =
                make_float4(acc[i][0]*inv, acc[i][1]*inv, acc[i][2]*inv, acc[i][3]*inv);
        }
    } else if (seg==1){
        #pragma unroll
        for (int i=0;i<8;i++){
            long row = row0 + tr*8 + i;
            *(float4*)&g_v[row*DD + tc*4] =
                make_float4(acc[i][0],acc[i][1],acc[i][2],acc[i][3]);
        }
    } else {
        float b1v[4], w2v[4];
        #pragma unroll
        for (int j=0;j<4;j++){ b1v[j]=ir_b1[tc*4+j]; w2v[j]=ir_w2[tc*4+j]; }
        float b2 = ir_b2[0];
        #pragma unroll
        for (int i=0;i<8;i++){
            float p = 0.f;
            #pragma unroll
            for (int j=0;j<4;j++) p += gelu_exact(acc[i][j]+b1v[j]) * w2v[j];
            p += __shfl_xor_sync(FULL, p, 1);
            p += __shfl_xor_sync(FULL, p, 2);
            p += __shfl_xor_sync(FULL, p, 4);
            p += __shfl_xor_sync(FULL, p, 8);
            if (tc==0){
                long row = row0 + tr*8 + i;
                g_us[row] = (p + b2) > 0.f ? 1.f : 0.f;
            }
        }
    }
}

// ---------------------------------------------------------------------------
// Kernel 2: pw = softmax(x @ pw_w + pw_b). warp per token.
// ---------------------------------------------------------------------------
__global__ void __launch_bounds__(256) pw_kernel(
    const float* __restrict__ x, const float* __restrict__ pw_w,
    const float* __restrict__ pw_b)
{
    __shared__ __align__(16) float pwT[3][2048];
    const int tid = threadIdx.x;
    for (int idx = tid; idx < 3*2048; idx += 256){
        int i = idx/3, cc = idx - i*3;
        pwT[cc][i] = pw_w[idx];
    }
    __syncthreads();
    const int warp = tid>>5, lane = tid&31;
    const float b0 = pw_b[0], b1 = pw_b[1], b2 = pw_b[2];
    const unsigned FULL = 0xffffffffu;
    for (int it8 = 0; it8 < 8; it8++){
        long tok = (long)blockIdx.x*64 + warp*8 + it8;
        const float* xr = x + tok*NN;
        float a0=0.f,a1=0.f,a2=0.f;
        #pragma unroll
        for (int it=0; it<16; it++){
            int off = it*128 + lane*4;
            float4 xv = *(const float4*)&xr[off];
            float4 w0 = *(const float4*)&pwT[0][off];
            float4 w1 = *(const float4*)&pwT[1][off];
            float4 w2 = *(const float4*)&pwT[2][off];
            a0 += xv.x*w0.x + xv.y*w0.y + xv.z*w0.z + xv.w*w0.w;
            a1 += xv.x*w1.x + xv.y*w1.y + xv.z*w1.z + xv.w*w1.w;
            a2 += xv.x*w2.x + xv.y*w2.y + xv.z*w2.z + xv.w*w2.w;
        }
        #pragma unroll
        for (int d=1; d<32; d<<=1){
            a0 += __shfl_xor_sync(FULL, a0, d);
            a1 += __shfl_xor_sync(FULL, a1, d);
            a2 += __shfl_xor_sync(FULL, a2, d);
        }
        if (lane==0){
            float l0=a0+b0, l1=a1+b1, l2=a2+b2;
            float m = fmaxf(l0, fmaxf(l1,l2));
            float e0=expf(l0-m), e1=expf(l1-m), e2=expf(l2-m);
            float inv = 1.0f/(e0+e1+e2);
            g_pw[tok*4+0]=e0*inv; g_pw[tok*4+1]=e1*inv;
            g_pw[tok*4+2]=e2*inv; g_pw[tok*4+3]=0.f;
        }
    }
}

// ---------------------------------------------------------------------------
// Kernel 3: nu = gelu(v @ nm_w1 + b1) @ nm_w2 + b2. warp per token.
// ---------------------------------------------------------------------------
__global__ void __launch_bounds__(256) nu_kernel(
    const float* __restrict__ nm_w1, const float* __restrict__ nm_b1,
    const float* __restrict__ nm_w2, const float* __restrict__ nm_b2)
{
    __shared__ float W1s[64*128];
    __shared__ float hs[8][128];
    __shared__ float vs[8][64];
    const int tid = threadIdx.x;
    for (int i = tid; i < 64*128; i += 256) W1s[i] = nm_w1[i];
    long tok0 = (long)blockIdx.x*8;
    for (int i = tid; i < 8*64; i += 256){
        int t = i>>6, r = i&63;
        vs[t][r] = g_v[(tok0+t)*DD + r];
    }
    __syncthreads();
    const int warp = tid>>5, lane = tid&31;
    #pragma unroll
    for (int ii=0;ii<4;ii++){
        int i = lane + ii*32;
        float a = nm_b1[i];
        #pragma unroll 8
        for (int r=0;r<64;r++) a = fmaf(vs[warp][r], W1s[r*128+i], a);
        hs[warp][i] = gelu_exact(a);
    }
    __syncwarp();
    #pragma unroll
    for (int jj=0;jj<2;jj++){
        int j = lane + jj*32;
        float a = nm_b2[j];
        #pragma unroll 8
        for (int i=0;i<128;i++) a = fmaf(hs[warp][i], __ldg(&nm_w2[i*64+j]), a);
        g_nu[(tok0+warp)*DD + j] = a;
    }
}

// ---------------------------------------------------------------------------
// Kernel 3b: per-quad cross dots. quad p = tokens 4p..4p+3. warp per quad.
// layout: [qk0..qk3, kk10,kk20,kk21,kk30,kk31,kk32, qx10,qx20,qx21,qx30,qx31,qx32]
// ---------------------------------------------------------------------------
__global__ void __launch_bounds__(256) dots4_kernel(){
    const int tid = threadIdx.x;
    const int warp = tid>>5, lane = tid&31;
    long p = (long)blockIdx.x*8 + warp;
    long t = p*4;
    float qa[4], qb[4], ka[4], kb[4];
    #pragma unroll
    for (int i=0;i<4;i++){
        qa[i] = g_q[(t+i)*DD+lane]; qb[i] = g_q[(t+i)*DD+32+lane];
        ka[i] = g_k[(t+i)*DD+lane]; kb[i] = g_k[(t+i)*DD+32+lane];
    }
    float r[16];
    r[0] = qa[0]*ka[0]+qb[0]*kb[0];
    r[1] = qa[1]*ka[1]+qb[1]*kb[1];
    r[2] = qa[2]*ka[2]+qb[2]*kb[2];
    r[3] = qa[3]*ka[3]+qb[3]*kb[3];
    r[4] = ka[1]*ka[0]+kb[1]*kb[0];
    r[5] = ka[2]*ka[0]+kb[2]*kb[0];
    r[6] = ka[2]*ka[1]+kb[2]*kb[1];
    r[7] = ka[3]*ka[0]+kb[3]*kb[0];
    r[8] = ka[3]*ka[1]+kb[3]*kb[1];
    r[9] = ka[3]*ka[2]+kb[3]*kb[2];
    r[10]= qa[1]*ka[0]+qb[1]*kb[0];
    r[11]= qa[2]*ka[0]+qb[2]*kb[0];
    r[12]= qa[2]*ka[1]+qb[2]*kb[1];
    r[13]= qa[3]*ka[0]+qb[3]*kb[0];
    r[14]= qa[3]*ka[1]+qb[3]*kb[1];
    r[15]= qa[3]*ka[2]+qb[3]*kb[2];
    const unsigned FULL = 0xffffffffu;
    #pragma unroll
    for (int d=1; d<32; d<<=1){
        #pragma unroll
        for (int j=0;j<16;j++) r[j] += __shfl_xor_sync(FULL, r[j], d);
    }
    if (lane==0){
        *(float4*)&g_dots[p*16+ 0] = make_float4(r[0], r[1], r[2], r[3]);
        *(float4*)&g_dots[p*16+ 4] = make_float4(r[4], r[5], r[6], r[7]);
        *(float4*)&g_dots[p*16+ 8] = make_float4(r[8], r[9], r[10],r[11]);
        *(float4*)&g_dots[p*16+12] = make_float4(r[12],r[13],r[14],r[15]);
    }
}

// ---------------------------------------------------------------------------
// Kernel 4: decoupled H-scan, 4 steps per iteration (blocked recurrence).
// grid (8,4), 128 threads = 4 independent warps; warp = 2 columns,
// 16 threads/column, thread owns rows sub*4..sub*4+3 of its column.
// All 16 shuffle-reduction chains per iteration are independent.
// ---------------------------------------------------------------------------
__global__ void __launch_bounds__(128,1) scan4_kernel(
    const float* __restrict__ fa_p, const float* __restrict__ sa_p)
{
    const int batch = blockIdx.y;
    const int lane  = threadIdx.x & 31;
    const int warp  = threadIdx.x >> 5;
    const int c     = blockIdx.x*8 + warp*2 + (lane>>4);
    const int sub   = lane & 15;
    const float fa = *fa_p, sa = *sa_p;
    const float ofa = 1.0f - fa, osa = 1.0f - sa;
    const float fa2 = fa*fa, fa3 = fa2*fa, fa4 = fa2*fa2;
    const float sa2 = sa*sa, sa3 = sa2*sa, sa4 = sa2*sa2;
    const unsigned FULL = 0xffffffffu;

    float F[4] = {0,0,0,0}, S[4] = {0,0,0,0};
    const long tb = (long)batch * SS;
    const long pb = (long)batch * (SS/4);

    float4 qv[4], kv[4], dt0, dt1, dt2, dt3;
    float vv[4], us[4];
    {
        long t = tb;
        #pragma unroll
        for (int i=0;i<4;i++){
            qv[i] = *(const float4*)&g_q[(t+i)*DD + sub*4];
            kv[i] = *(const float4*)&g_k[(t+i)*DD + sub*4];
            vv[i] = g_v[(t+i)*DD + c];
            us[i] = g_us[t+i];
        }
        dt0 = *(const float4*)&g_dots[pb*16+ 0];
        dt1 = *(const float4*)&g_dots[pb*16+ 4];
        dt2 = *(const float4*)&g_dots[pb*16+ 8];
        dt3 = *(const float4*)&g_dots[pb*16+12];
    }

    for (int p = 0; p < SS/4; p++){
        const long t = tb + (long)p*4;
        float ka[4][4], qa[4][4];
        #pragma unroll
        for (int i=0;i<4;i++){
            ka[i][0]=kv[i].x; ka[i][1]=kv[i].y; ka[i][2]=kv[i].z; ka[i][3]=kv[i].w;
            qa[i][0]=qv[i].x; qa[i][1]=qv[i].y; qa[i][2]=qv[i].z; qa[i][3]=qv[i].w;
        }
        const float qk0=dt0.x, qk1=dt0.y, qk2=dt0.z, qk3=dt0.w;
        const float kk10=dt1.x, kk20=dt1.y, kk21=dt1.z, kk30=dt1.w;
        const float kk31=dt2.x, kk32=dt2.y, qx10=dt2.z, qx20=dt2.w;
        const float qx21=dt3.x, qx30=dt3.y, qx31=dt3.z, qx32=dt3.w;
        float v0=vv[0], v1=vv[1], v2=vv[2], v3=vv[3];
        float gS0=osa*us[0], gS1=osa*us[1], gS2=osa*us[2], gS3=osa*us[3];

        // 16 independent partial dots against chunk-entry states
        float red[16];
        #pragma unroll
        for (int j=0;j<16;j++) red[j]=0.f;
        #pragma unroll
        for (int r=0;r<4;r++){
            red[0]  = fmaf(ka[0][r], F[r], red[0]);   // kF0
            red[1]  = fmaf(ka[1][r], F[r], red[1]);
            red[2]  = fmaf(ka[2][r], F[r], red[2]);
            red[3]  = fmaf(ka[3][r], F[r], red[3]);
            red[4]  = fmaf(qa[0][r], F[r], red[4]);   // qF0
            red[5]  = fmaf(qa[1][r], F[r], red[5]);
            red[6]  = fmaf(qa[2][r], F[r], red[6]);
            red[7]  = fmaf(qa[3][r], F[r], red[7]);
            red[8]  = fmaf(ka[0][r], S[r], red[8]);   // kS0
            red[9]  = fmaf(ka[1][r], S[r], red[9]);
            red[10] = fmaf(ka[2][r], S[r], red[10]);
            red[11] = fmaf(ka[3][r], S[r], red[11]);
            red[12] = fmaf(qa[0][r], S[r], red[12]);  // qS0
            red[13] = fmaf(qa[1][r], S[r], red[13]);
            red[14] = fmaf(qa[2][r], S[r], red[14]);
            red[15] = fmaf(qa[3][r], S[r], red[15]);
        }

        // prefetch next quad (consumed next iteration; hidden under reduce+scalar)
        float4 nq[4], nk[4], nd0, nd1, nd2, nd3;
        float nv[4], nu_[4];
        if (p+1 < SS/4){
            long tn = t + 4;
            #pragma unroll
            for (int i=0;i<4;i++){
                nq[i] = *(const float4*)&g_q[(tn+i)*DD + sub*4];
                nk[i] = *(const float4*)&g_k[(tn+i)*DD + sub*4];
                nv[i] = g_v[(tn+i)*DD + c];
                nu_[i] = g_us[tn+i];
            }
            long pp = pb + p + 1;
            nd0 = *(const float4*)&g_dots[pp*16+ 0];
            nd1 = *(const float4*)&g_dots[pp*16+ 4];
            nd2 = *(const float4*)&g_dots[pp*16+ 8];
            nd3 = *(const float4*)&g_dots[pp*16+12];
        } else {
            nq[0]=qv[0];nq[1]=qv[1];nq[2]=qv[2];nq[3]=qv[3];
            nk[0]=kv[0];nk[1]=kv[1];nk[2]=kv[2];nk[3]=kv[3];
            nv[0]=v0;nv[1]=v1;nv[2]=v2;nv[3]=v3;
            nu_[0]=us[0];nu_[1]=us[1];nu_[2]=us[2];nu_[3]=us[3];
            nd0=dt0;nd1=dt1;nd2=dt2;nd3=dt3;
        }

        // column-wide reduction: 16 independent 4-stage chains
        #pragma unroll
        for (int d=1; d<16; d<<=1){
            #pragma unroll
            for (int j=0;j<16;j++) red[j] += __shfl_xor_sync(FULL, red[j], d);
        }
        const float kF0=red[0], kF1=red[1], kF2=red[2], kF3=red[3];
        const float qF0=red[4], qF1=red[5], qF2=red[6], qF3=red[7];
        const float kS0=red[8], kS1=red[9], kS2=red[10], kS3=red[11];
        const float qS0=red[12], qS1=red[13], qS2=red[14], qS3=red[15];

        // blocked scalar recurrence (per column)
        float cF0 = ofa*(v0 - kF0);
        float cS0 = gS0*(v0 - kS0);
        float DhF1 = fmaf(kk10, cF0, fa*kF1);
        float DhS1 = fmaf(kk10, cS0, sa*kS1);
        float cF1 = ofa*(v1 - DhF1);
        float cS1 = gS1*(v1 - DhS1);
        float DhF2 = fa2*kF2 + fa*kk20*cF0 + kk21*cF1;
        float DhS2 = sa2*kS2 + sa*kk20*cS0 + kk21*cS1;
        float cF2 = ofa*(v2 - DhF2);
        float cS2 = gS2*(v2 - DhS2);
        float DhF3 = fa3*kF3 + fa2*kk30*cF0 + fa*kk31*cF1 + kk32*cF2;
        float DhS3 = sa3*kS3 + sa2*kk30*cS0 + sa*kk31*cS1 + kk32*cS2;
        float cF3 = ofa*(v3 - DhF3);
        float cS3 = gS3*(v3 - DhS3);

        float PqF0 = qF0;
        float PqS0 = qS0;
        float PqF1 = fmaf(qx10, cF0, fa*qF1);
        float PqS1 = fmaf(qx10, cS0, sa*qS1);
        float PqF2 = fa2*qF2 + fa*qx20*cF0 + qx21*cF1;
        float PqS2 = sa2*qS2 + sa*qx20*cS0 + qx21*cS1;
        float PqF3 = fa3*qF3 + fa2*qx30*cF0 + fa*qx31*cF1 + qx32*cF2;
        float PqS3 = sa3*qS3 + sa2*qx30*cS0 + sa*qx31*cS1 + qx32*cS2;

        float oF0 = fmaf(qk0, cF0, fa*PqF0);
        float oF1 = fmaf(qk1, cF1, fa*PqF1);
        float oF2 = fmaf(qk2, cF2, fa*PqF2);
        float oF3 = fmaf(qk3, cF3, fa*PqF3);
        float oS0 = fmaf(qk0, cS0, sa*PqS0);
        float oS1 = fmaf(qk1, cS1, sa*PqS1);
        float oS2 = fmaf(qk2, cS2, sa*PqS2);
        float oS3 = fmaf(qk3, cS3, sa*PqS3);

        float e0 = v0 - 0.5f*(PqF0+PqS0); e0*=e0;
        float e1 = v1 - 0.5f*(PqF1+PqS1); e1*=e1;
        float e2 = v2 - 0.5f*(PqF2+PqS2); e2*=e2;
        float e3 = v3 - 0.5f*(PqF3+PqS3); e3*=e3;

        // state update: H <- a^4 H + sum_j a^(3-j) c_j k_j
        float wF0=fa3*cF0, wF1=fa2*cF1, wF2=fa*cF2, wF3=cF3;
        float wS0=sa3*cS0, wS1=sa2*cS1, wS2=sa*cS2, wS3=cS3;
        #pragma unroll
        for (int r=0;r<4;r++){
            F[r] = fa4*F[r] + wF0*ka[0][r] + wF1*ka[1][r] + wF2*ka[2][r] + wF3*ka[3][r];
            S[r] = sa4*S[r] + wS0*ka[0][r] + wS1*ka[1][r] + wS2*ka[2][r] + wS3*ka[3][r];
        }

        if (sub == 0){
            g_outf[(t+0)*DD + c]=oF0; g_outf[(t+1)*DD + c]=oF1;
            g_outf[(t+2)*DD + c]=oF2; g_outf[(t+3)*DD + c]=oF3;
            g_outs[(t+0)*DD + c]=oS0; g_outs[(t+1)*DD + c]=oS1;
            g_outs[(t+2)*DD + c]=oS2; g_outs[(t+3)*DD + c]=oS3;
            g_ec[(t+0)*DD + c]=e0; g_ec[(t+1)*DD + c]=e1;
            g_ec[(t+2)*DD + c]=e2; g_ec[(t+3)*DD + c]=e3;
        }

        #pragma unroll
        for (int i=0;i<4;i++){ qv[i]=nq[i]; kv[i]=nk[i]; vv[i]=nv[i]; us[i]=nu_[i]; }
        dt0=nd0; dt1=nd1; dt2=nd2; dt3=nd3;
    }
}

// ---------------------------------------------------------------------------
// Kernel 5: gate = (sum_c e_c > thr) ? 0.1 : 0. warp per token.
// ---------------------------------------------------------------------------
__global__ void __launch_bounds__(256) gate_kernel(){
    const int tid = threadIdx.x;
    const int warp = tid>>5, lane = tid&31;
    long tok = (long)blockIdx.x*8 + warp;
    float s = g_ec[tok*DD + lane] + g_ec[tok*DD + 32 + lane];
    const unsigned FULL = 0xffffffffu;
    #pragma unroll
    for (int d=1; d<32; d<<=1) s += __shfl_xor_sync(FULL,s,d);
    if (lane==0){
        // sigmoid(err/(1+1e-6)) > 0.7  <=>  err > ln(7/3)*(1+1e-6)
        g_gate[tok] = (s > 0.84729871f) ? 0.1f : 0.0f;
    }
}

// ---------------------------------------------------------------------------
// Kernel 6: ns scan + pw combine, unroll-8 with batched prefetch.
// ---------------------------------------------------------------------------
__global__ void __launch_bounds__(64,1) ns_kernel(){
    const int b = blockIdx.x;
    const int c = threadIdx.x;
    const long tb = (long)b*SS;
    float ns = 0.f;
    for (int tt=0; tt<SS; tt+=8){
        float gg[8], nn[8], of[8], os[8];
        float4 pw4[8];
        #pragma unroll
        for (int j=0;j<8;j++){
            long tok = tb + tt + j;
            gg[j] = g_gate[tok];
            nn[j] = g_nu[tok*DD + c];
            of[j] = g_outf[tok*DD + c];
            os[j] = g_outs[tok*DD + c];
            pw4[j] = *(const float4*)&g_pw[tok*4];
        }
        #pragma unroll
        for (int j=0;j<8;j++){
            ns = fmaf(gg[j], nn[j] - ns, ns);
            g_outpre[(tb+tt+j)*DD + c] =
                pw4[j].x*of[j] + pw4[j].y*os[j] + pw4[j].z*ns;
        }
    }
}

// ---------------------------------------------------------------------------
// Kernel 7: RMSNorm. warp per row.
// ---------------------------------------------------------------------------
__global__ void __launch_bounds__(256) rms_kernel(const float* __restrict__ norm_w){
    long row = (long)blockIdx.x*8 + (threadIdx.x>>5);
    int lane = threadIdx.x & 31;
    float x0 = g_outpre[row*DD + lane];
    float x1 = g_outpre[row*DD + 32 + lane];
    float ss = x0*x0 + x1*x1;
    #pragma unroll
    for (int d=1; d<32; d<<=1) ss += __shfl_xor_sync(0xffffffffu, ss, d);
    float inv = rsqrtf(ss*(1.0f/64.0f) + 1e-6f);
    g_a[row*DD + lane]      = x0*inv*norm_w[lane];
    g_a[row*DD + 32 + lane] = x1*inv*norm_w[32+lane];
}

// ---------------------------------------------------------------------------
// Kernel 8: out = g_a[8192,64] @ Wo[64,2048]. 64x64 tiles.
// ---------------------------------------------------------------------------
__global__ void __launch_bounds__(256,2) outgemm_kernel(
    const float* __restrict__ Wo, float* __restrict__ out)
{
    __shared__ __align__(16) float AsT[64][68];
    __shared__ __align__(16) float Bs[64][68];
    const int n0   = blockIdx.x*64;
    const int row0 = blockIdx.y*64;
    const int tid  = threadIdx.x;
    #pragma unroll
    for (int l=0;l<4;l++){
        int s = tid + l*256;
        int rr = s>>4, kq = s&15;
        float4 a4 = *(const float4*)&g_a[(long)(row0+rr)*DD + kq*4];
        AsT[kq*4+0][rr]=a4.x; AsT[kq*4+1][rr]=a4.y;
        AsT[kq*4+2][rr]=a4.z; AsT[kq*4+3][rr]=a4.w;
        float4 b4 = *(const float4*)&Wo[(long)rr*NN + n0 + kq*4];
        *(float4*)&Bs[rr][kq*4] = b4;
    }
    __syncthreads();
    const int tr = tid>>4, tc = tid&15;
    float acc[4][4];
    #pragma unroll
    for (int i=0;i<4;i++)
        #pragma unroll
        for (int j=0;j<4;j++) acc[i][j]=0.f;
    #pragma unroll 8
    for (int k=0;k<64;k++){
        float4 a4 = *(const float4*)&AsT[k][tr*4];
        float4 b4 = *(const float4*)&Bs[k][tc*4];
        float am[4]={a4.x,a4.y,a4.z,a4.w}, bn[4]={b4.x,b4.y,b4.z,b4.w};
        #pragma unroll
        for (int i=0;i<4;i++)
            #pragma unroll
            for (int j=0;j<4;j++) acc[i][j]=fmaf(am[i],bn[j],acc[i][j]);
    }
    #pragma unroll
    for (int i=0;i<4;i++){
        *(float4*)&out[(long)(row0+tr*4+i)*NN + n0 + tc*4] =
            make_float4(acc[i][0],acc[i][1],acc[i][2],acc[i][3]);
    }
}

extern "C" void kernel_launch(void* const* d_in, const int* in_sizes, int n_in,
                              void* d_out, int out_size)
{
    const float* x      = (const float*)d_in[0];
    const float* Wk     = (const float*)d_in[1];
    const float* Wv     = (const float*)d_in[2];
    const float* Wq     = (const float*)d_in[3];
    const float* fa     = (const float*)d_in[4];
    const float* sa     = (const float*)d_in[5];
    const float* nm_w1  = (const float*)d_in[6];
    const float* nm_b1  = (const float*)d_in[7];
    const float* nm_w2  = (const float*)d_in[8];
    const float* nm_b2  = (const float*)d_in[9];
    const float* ir_w1  = (const float*)d_in[10];
    const float* ir_b1  = (const float*)d_in[11];
    const float* ir_w2  = (const float*)d_in[12];
    const float* ir_b2  = (const float*)d_in[13];
    const float* pw_w   = (const float*)d_in[14];
    const float* pw_b   = (const float*)d_in[15];
    const float* Wo     = (const float*)d_in[16];
    const float* norm_w = (const float*)d_in[17];
    float* out = (float*)d_out;

    // scan4_kernel kept at launch position 3 for the ncu -s 5 -c 1 slot.
    pw_kernel<<<128, 256>>>(x, pw_w, pw_b);
    proj_kernel<<<dim3(64,4), 256>>>(x, Wk, Wv, Wq, ir_w1, ir_b1, ir_w2, ir_b2);
    dots4_kernel<<<256, 256>>>();
    scan4_kernel<<<dim3(8,4), 128>>>(fa, sa);
    nu_kernel<<<1024, 256>>>(nm_w1, nm_b1, nm_w2, nm_b2);
    gate_kernel<<<1024, 256>>>();
    ns_kernel<<<4, 64>>>();
    rms_kernel<<<1024, 256>>>(norm_w);
    outgemm_kernel<<<dim3(32,128), 256>>>(Wo, out);
}

// round 9
// speedup vs baseline: 2.0481x; 1.0407x over previous
#include <cuda_runtime.h>
#include <cuda_bf16.h>
#include <math.h>

#define BB 4
#define SS 2048
#define DD 64
#define NN 2048
#define NTOK (BB*SS)
#define NQUAD (NTOK/4)

// -------- static device scratch (no allocations allowed) ----------
__device__ float g_k[NTOK*DD];
__device__ float g_q[NTOK*DD];
__device__ float g_v[NTOK*DD];
__device__ float g_nu[NTOK*DD];
__device__ float g_pw[NTOK*4];
__device__ float g_us[NTOK];
__device__ float g_outf[NTOK*DD];
__device__ float g_outs[NTOK*DD];
__device__ float g_pqf[NTOK*DD];
__device__ float g_pqs[NTOK*DD];
__device__ float g_dots[NQUAD*16];
__device__ float g_gate[NTOK];
__device__ float g_outpre[NTOK*DD];
__device__ float g_a[NTOK*DD];

__device__ __forceinline__ float gelu_exact(float x){
    return 0.5f*x*(1.0f + erff(x*0.70710678118654752f));
}

// ---------------------------------------------------------------------------
// Kernel 1: fused projection GEMMs. grid (64 row-tiles, 4 segments), 256 thr.
// ---------------------------------------------------------------------------
__global__ void __launch_bounds__(256,2) proj_kernel(
    const float* __restrict__ x,
    const float* __restrict__ Wk, const float* __restrict__ Wv,
    const float* __restrict__ Wq, const float* __restrict__ ir_w1,
    const float* __restrict__ ir_b1, const float* __restrict__ ir_w2,
    const float* __restrict__ ir_b2)
{
    __shared__ __align__(16) float As[2][16][132];
    __shared__ __align__(16) float Bs[2][16][68];

    const int seg  = blockIdx.y;
    const int row0 = blockIdx.x * 128;
    const float* __restrict__ B = (seg==0)?Wk:(seg==1)?Wv:(seg==2)?Wq:ir_w1;

    const int tid = threadIdx.x;
    const int tr = tid >> 4;
    const int tc = tid & 15;

    float acc[8][4];
    #pragma unroll
    for (int i=0;i<8;i++)
        #pragma unroll
        for (int j=0;j<4;j++) acc[i][j]=0.f;

    float4 ra[2]; float4 rb;

    {
        #pragma unroll
        for (int j=0;j<2;j++){
            int s = tid*2 + j;
            int m = s >> 2, k4 = s & 3;
            ra[j] = *(const float4*)&x[(long)(row0+m)*NN + k4*4];
        }
        { int kk = tid >> 4, c4 = tid & 15;
          rb = *(const float4*)&B[(long)kk*DD + c4*4]; }
        #pragma unroll
        for (int j=0;j<2;j++){
            int s = tid*2+j; int m = s>>2, k4 = s&3;
            As[0][k4*4+0][m]=ra[j].x; As[0][k4*4+1][m]=ra[j].y;
            As[0][k4*4+2][m]=ra[j].z; As[0][k4*4+3][m]=ra[j].w;
        }
        { int kk=tid>>4, c4=tid&15; *(float4*)&Bs[0][kk][c4*4] = rb; }
    }
    __syncthreads();

    for (int c=0; c<128; c++){
        const int buf = c & 1;
        if (c+1 < 128){
            int k0 = (c+1)*16;
            #pragma unroll
            for (int j=0;j<2;j++){
                int s = tid*2 + j; int m = s>>2, k4 = s&3;
                ra[j] = *(const float4*)&x[(long)(row0+m)*NN + k0 + k4*4];
            }
            int kk = tid>>4, c4 = tid&15;
            rb = *(const float4*)&B[(long)(k0+kk)*DD + c4*4];
        }
        #pragma unroll
        for (int kk=0; kk<16; kk++){
            float4 a0 = *(float4*)&As[buf][kk][tr*8];
            float4 a1 = *(float4*)&As[buf][kk][tr*8+4];
            float4 bb = *(float4*)&Bs[buf][kk][tc*4];
            float am[8] = {a0.x,a0.y,a0.z,a0.w,a1.x,a1.y,a1.z,a1.w};
            float bn[4] = {bb.x,bb.y,bb.z,bb.w};
            #pragma unroll
            for (int i=0;i<8;i++)
                #pragma unroll
                for (int j=0;j<4;j++) acc[i][j] = fmaf(am[i], bn[j], acc[i][j]);
        }
        if (c+1 < 128){
            int nb = (c+1)&1;
            #pragma unroll
            for (int j=0;j<2;j++){
                int s = tid*2+j; int m=s>>2,k4=s&3;
                As[nb][k4*4+0][m]=ra[j].x; As[nb][k4*4+1][m]=ra[j].y;
                As[nb][k4*4+2][m]=ra[j].z; As[nb][k4*4+3][m]=ra[j].w;
            }
            int kk=tid>>4,c4=tid&15;
            *(float4*)&Bs[nb][kk][c4*4]=rb;
        }
        __syncthreads();
    }

    const unsigned FULL = 0xffffffffu;
    if (seg==0 || seg==2){
        float* dst = (seg==0)? g_k : g_q;
        #pragma unroll
        for (int i=0;i<8;i++){
            float s = acc[i][0]*acc[i][0]+acc[i][1]*acc[i][1]
                    + acc[i][2]*acc[i][2]+acc[i][3]*acc[i][3];
            s += __shfl_xor_sync(FULL, s, 1);
            s += __shfl_xor_sync(FULL, s, 2);
            s += __shfl_xor_sync(FULL, s, 4);
            s += __shfl_xor_sync(FULL, s, 8);
            float inv = 1.0f / fmaxf(sqrtf(s), 1e-12f);
            long row = row0 + tr*8 + i;
            *(float4*)&dst[row*DD + tc*4] =
                make_float4(acc[i][0]*inv, acc[i][1]*inv, acc[i][2]*inv, acc[i][3]*inv);
        }
    } else if (seg==1){
        #pragma unroll
        for (int i=0;i<8;i++){
            long row = row0 + tr*8 + i;
            *(float4*)&g_v[row*DD + tc*4] =
                make_float4(acc[i][0],acc[i][1],acc[i][2],acc[i][3]);
        }
    } else {
        float b1v[4], w2v[4];
        #pragma unroll
        for (int j=0;j<4;j++){ b1v[j]=ir_b1[tc*4+j]; w2v[j]=ir_w2[tc*4+j]; }
        float b2 = ir_b2[0];
        #pragma unroll
        for (int i=0;i<8;i++){
            float p = 0.f;
            #pragma unroll
            for (int j=0;j<4;j++) p += gelu_exact(acc[i][j]+b1v[j]) * w2v[j];
            p += __shfl_xor_sync(FULL, p, 1);
            p += __shfl_xor_sync(FULL, p, 2);
            p += __shfl_xor_sync(FULL, p, 4);
            p += __shfl_xor_sync(FULL, p, 8);
            if (tc==0){
                long row = row0 + tr*8 + i;
                g_us[row] = (p + b2) > 0.f ? 1.f : 0.f;
            }
        }
    }
}

// ---------------------------------------------------------------------------
// Kernel 2: pw = softmax(x @ pw_w + pw_b). warp per token.
// ---------------------------------------------------------------------------
__global__ void __launch_bounds__(256) pw_kernel(
    const float* __restrict__ x, const float* __restrict__ pw_w,
    const float* __restrict__ pw_b)
{
    __shared__ __align__(16) float pwT[3][2048];
    const int tid = threadIdx.x;
    for (int idx = tid; idx < 3*2048; idx += 256){
        int i = idx/3, cc = idx - i*3;
        pwT[cc][i] = pw_w[idx];
    }
    __syncthreads();
    const int warp = tid>>5, lane = tid&31;
    const float b0 = pw_b[0], b1 = pw_b[1], b2 = pw_b[2];
    const unsigned FULL = 0xffffffffu;
    for (int it8 = 0; it8 < 8; it8++){
        long tok = (long)blockIdx.x*64 + warp*8 + it8;
        const float* xr = x + tok*NN;
        float a0=0.f,a1=0.f,a2=0.f;
        #pragma unroll
        for (int it=0; it<16; it++){
            int off = it*128 + lane*4;
            float4 xv = *(const float4*)&xr[off];
            float4 w0 = *(const float4*)&pwT[0][off];
            float4 w1 = *(const float4*)&pwT[1][off];
            float4 w2 = *(const float4*)&pwT[2][off];
            a0 += xv.x*w0.x + xv.y*w0.y + xv.z*w0.z + xv.w*w0.w;
            a1 += xv.x*w1.x + xv.y*w1.y + xv.z*w1.z + xv.w*w1.w;
            a2 += xv.x*w2.x + xv.y*w2.y + xv.z*w2.z + xv.w*w2.w;
        }
        #pragma unroll
        for (int d=1; d<32; d<<=1){
            a0 += __shfl_xor_sync(FULL, a0, d);
            a1 += __shfl_xor_sync(FULL, a1, d);
            a2 += __shfl_xor_sync(FULL, a2, d);
        }
        if (lane==0){
            float l0=a0+b0, l1=a1+b1, l2=a2+b2;
            float m = fmaxf(l0, fmaxf(l1,l2));
            float e0=expf(l0-m), e1=expf(l1-m), e2=expf(l2-m);
            float inv = 1.0f/(e0+e1+e2);
            g_pw[tok*4+0]=e0*inv; g_pw[tok*4+1]=e1*inv;
            g_pw[tok*4+2]=e2*inv; g_pw[tok*4+3]=0.f;
        }
    }
}

// ---------------------------------------------------------------------------
// Kernel 3: nu = gelu(v @ nm_w1 + b1) @ nm_w2 + b2. warp per token.
// ---------------------------------------------------------------------------
__global__ void __launch_bounds__(256) nu_kernel(
    const float* __restrict__ nm_w1, const float* __restrict__ nm_b1,
    const float* __restrict__ nm_w2, const float* __restrict__ nm_b2)
{
    __shared__ float W1s[64*128];
    __shared__ float hs[8][128];
    __shared__ float vs[8][64];
    const int tid = threadIdx.x;
    for (int i = tid; i < 64*128; i += 256) W1s[i] = nm_w1[i];
    long tok0 = (long)blockIdx.x*8;
    for (int i = tid; i < 8*64; i += 256){
        int t = i>>6, r = i&63;
        vs[t][r] = g_v[(tok0+t)*DD + r];
    }
    __syncthreads();
    const int warp = tid>>5, lane = tid&31;
    #pragma unroll
    for (int ii=0;ii<4;ii++){
        int i = lane + ii*32;
        float a = nm_b1[i];
        #pragma unroll 8
        for (int r=0;r<64;r++) a = fmaf(vs[warp][r], W1s[r*128+i], a);
        hs[warp][i] = gelu_exact(a);
    }
    __syncwarp();
    #pragma unroll
    for (int jj=0;jj<2;jj++){
        int j = lane + jj*32;
        float a = nm_b2[j];
        #pragma unroll 8
        for (int i=0;i<128;i++) a = fmaf(hs[warp][i], __ldg(&nm_w2[i*64+j]), a);
        g_nu[(tok0+warp)*DD + j] = a;
    }
}

// ---------------------------------------------------------------------------
// Kernel 3b: per-quad cross dots. quad p = tokens 4p..4p+3. warp per quad.
// ---------------------------------------------------------------------------
__global__ void __launch_bounds__(256) dots4_kernel(){
    const int tid = threadIdx.x;
    const int warp = tid>>5, lane = tid&31;
    long p = (long)blockIdx.x*8 + warp;
    long t = p*4;
    float qa[4], qb[4], ka[4], kb[4];
    #pragma unroll
    for (int i=0;i<4;i++){
        qa[i] = g_q[(t+i)*DD+lane]; qb[i] = g_q[(t+i)*DD+32+lane];
        ka[i] = g_k[(t+i)*DD+lane]; kb[i] = g_k[(t+i)*DD+32+lane];
    }
    float r[16];
    r[0] = qa[0]*ka[0]+qb[0]*kb[0];
    r[1] = qa[1]*ka[1]+qb[1]*kb[1];
    r[2] = qa[2]*ka[2]+qb[2]*kb[2];
    r[3] = qa[3]*ka[3]+qb[3]*kb[3];
    r[4] = ka[1]*ka[0]+kb[1]*kb[0];
    r[5] = ka[2]*ka[0]+kb[2]*kb[0];
    r[6] = ka[2]*ka[1]+kb[2]*kb[1];
    r[7] = ka[3]*ka[0]+kb[3]*kb[0];
    r[8] = ka[3]*ka[1]+kb[3]*kb[1];
    r[9] = ka[3]*ka[2]+kb[3]*kb[2];
    r[10]= qa[1]*ka[0]+qb[1]*kb[0];
    r[11]= qa[2]*ka[0]+qb[2]*kb[0];
    r[12]= qa[2]*ka[1]+qb[2]*kb[1];
    r[13]= qa[3]*ka[0]+qb[3]*kb[0];
    r[14]= qa[3]*ka[1]+qb[3]*kb[1];
    r[15]= qa[3]*ka[2]+qb[3]*kb[2];
    const unsigned FULL = 0xffffffffu;
    #pragma unroll
    for (int d=1; d<32; d<<=1){
        #pragma unroll
        for (int j=0;j<16;j++) r[j] += __shfl_xor_sync(FULL, r[j], d);
    }
    if (lane==0){
        *(float4*)&g_dots[p*16+ 0] = make_float4(r[0], r[1], r[2], r[3]);
        *(float4*)&g_dots[p*16+ 4] = make_float4(r[4], r[5], r[6], r[7]);
        *(float4*)&g_dots[p*16+ 8] = make_float4(r[8], r[9], r[10],r[11]);
        *(float4*)&g_dots[p*16+12] = make_float4(r[12],r[13],r[14],r[15]);
    }
}

// ---------------------------------------------------------------------------
// Kernel 4: split H-scan, 4 steps/iter. grid (8, 4, 2): z=0 fast, z=1 slow.
// 128 thr = 4 warps; warp = 2 columns, 16 thr/column, thread owns 4 rows.
// Writes out{f|s} and Pq{f|s}; error reconstructed later in gate_kernel.
// ---------------------------------------------------------------------------
__global__ void __launch_bounds__(128,1) scanFS_kernel(
    const float* __restrict__ fa_p, const float* __restrict__ sa_p)
{
    const int is_slow = blockIdx.z;
    const int batch = blockIdx.y;
    const int lane  = threadIdx.x & 31;
    const int warp  = threadIdx.x >> 5;
    const int c     = blockIdx.x*8 + warp*2 + (lane>>4);
    const int sub   = lane & 15;
    const float a  = is_slow ? *sa_p : *fa_p;
    const float oa = 1.0f - a;
    const float a2 = a*a, a3 = a2*a, a4 = a2*a2;
    float* __restrict__ outp = is_slow ? g_outs : g_outf;
    float* __restrict__ pqp  = is_slow ? g_pqs  : g_pqf;
    const unsigned FULL = 0xffffffffu;

    float H[4] = {0,0,0,0};
    const long tb = (long)batch * SS;
    const long pb = (long)batch * (SS/4);

    float4 qv[4], kv[4], dt0, dt1, dt2, dt3;
    float vv[4], gg[4];
    {
        long t = tb;
        #pragma unroll
        for (int i=0;i<4;i++){
            qv[i] = *(const float4*)&g_q[(t+i)*DD + sub*4];
            kv[i] = *(const float4*)&g_k[(t+i)*DD + sub*4];
            vv[i] = g_v[(t+i)*DD + c];
            gg[i] = is_slow ? oa*g_us[t+i] : oa;
        }
        dt0 = *(const float4*)&g_dots[pb*16+ 0];
        dt1 = *(const float4*)&g_dots[pb*16+ 4];
        dt2 = *(const float4*)&g_dots[pb*16+ 8];
        dt3 = *(const float4*)&g_dots[pb*16+12];
    }

    for (int p = 0; p < SS/4; p++){
        const long t = tb + (long)p*4;
        float ka[4][4], qa[4][4];
        #pragma unroll
        for (int i=0;i<4;i++){
            ka[i][0]=kv[i].x; ka[i][1]=kv[i].y; ka[i][2]=kv[i].z; ka[i][3]=kv[i].w;
            qa[i][0]=qv[i].x; qa[i][1]=qv[i].y; qa[i][2]=qv[i].z; qa[i][3]=qv[i].w;
        }
        const float qk0=dt0.x, qk1=dt0.y, qk2=dt0.z, qk3=dt0.w;
        const float kk10=dt1.x, kk20=dt1.y, kk21=dt1.z, kk30=dt1.w;
        const float kk31=dt2.x, kk32=dt2.y, qx10=dt2.z, qx20=dt2.w;
        const float qx21=dt3.x, qx30=dt3.y, qx31=dt3.z, qx32=dt3.w;
        const float v0=vv[0], v1=vv[1], v2=vv[2], v3=vv[3];
        const float g0=gg[0], g1=gg[1], g2=gg[2], g3=gg[3];

        // 8 independent partial dots against chunk-entry state
        float red[8];
        #pragma unroll
        for (int j=0;j<8;j++) red[j]=0.f;
        #pragma unroll
        for (int r=0;r<4;r++){
            red[0] = fmaf(ka[0][r], H[r], red[0]);
            red[1] = fmaf(ka[1][r], H[r], red[1]);
            red[2] = fmaf(ka[2][r], H[r], red[2]);
            red[3] = fmaf(ka[3][r], H[r], red[3]);
            red[4] = fmaf(qa[0][r], H[r], red[4]);
            red[5] = fmaf(qa[1][r], H[r], red[5]);
            red[6] = fmaf(qa[2][r], H[r], red[6]);
            red[7] = fmaf(qa[3][r], H[r], red[7]);
        }

        // prefetch next quad
        float4 nq[4], nk[4], nd0, nd1, nd2, nd3;
        float nv[4], ng[4];
        if (p+1 < SS/4){
            long tn = t + 4;
            #pragma unroll
            for (int i=0;i<4;i++){
                nq[i] = *(const float4*)&g_q[(tn+i)*DD + sub*4];
                nk[i] = *(const float4*)&g_k[(tn+i)*DD + sub*4];
                nv[i] = g_v[(tn+i)*DD + c];
                ng[i] = is_slow ? oa*g_us[tn+i] : oa;
            }
            long pp = pb + p + 1;
            nd0 = *(const float4*)&g_dots[pp*16+ 0];
            nd1 = *(const float4*)&g_dots[pp*16+ 4];
            nd2 = *(const float4*)&g_dots[pp*16+ 8];
            nd3 = *(const float4*)&g_dots[pp*16+12];
        } else {
            nq[0]=qv[0];nq[1]=qv[1];nq[2]=qv[2];nq[3]=qv[3];
            nk[0]=kv[0];nk[1]=kv[1];nk[2]=kv[2];nk[3]=kv[3];
            nv[0]=v0;nv[1]=v1;nv[2]=v2;nv[3]=v3;
            ng[0]=g0;ng[1]=g1;ng[2]=g2;ng[3]=g3;
            nd0=dt0;nd1=dt1;nd2=dt2;nd3=dt3;
        }

        // column-wide reduction: 8 independent 4-stage chains
        #pragma unroll
        for (int d=1; d<16; d<<=1){
            #pragma unroll
            for (int j=0;j<8;j++) red[j] += __shfl_xor_sync(FULL, red[j], d);
        }
        const float kH0=red[0], kH1=red[1], kH2=red[2], kH3=red[3];
        const float qH0=red[4], qH1=red[5], qH2=red[6], qH3=red[7];

        // blocked scalar recurrence
        float c0 = g0*(v0 - kH0);
        float Dh1 = fmaf(kk10, c0, a*kH1);
        float c1 = g1*(v1 - Dh1);
        float Dh2 = a2*kH2 + a*kk20*c0 + kk21*c1;
        float c2 = g2*(v2 - Dh2);
        float Dh3 = a3*kH3 + a2*kk30*c0 + a*kk31*c1 + kk32*c2;
        float c3 = g3*(v3 - Dh3);

        float Pq0 = qH0;
        float Pq1 = fmaf(qx10, c0, a*qH1);
        float Pq2 = a2*qH2 + a*qx20*c0 + qx21*c1;
        float Pq3 = a3*qH3 + a2*qx30*c0 + a*qx31*c1 + qx32*c2;

        float o0 = fmaf(qk0, c0, a*Pq0);
        float o1 = fmaf(qk1, c1, a*Pq1);
        float o2 = fmaf(qk2, c2, a*Pq2);
        float o3 = fmaf(qk3, c3, a*Pq3);

        // state update: H <- a^4 H + sum_j a^(3-j) c_j k_j
        float w0=a3*c0, w1=a2*c1, w2=a*c2, w3=c3;
        #pragma unroll
        for (int r=0;r<4;r++){
            H[r] = a4*H[r] + w0*ka[0][r] + w1*ka[1][r] + w2*ka[2][r] + w3*ka[3][r];
        }

        if (sub == 0){
            outp[(t+0)*DD + c]=o0; outp[(t+1)*DD + c]=o1;
            outp[(t+2)*DD + c]=o2; outp[(t+3)*DD + c]=o3;
            pqp[(t+0)*DD + c]=Pq0; pqp[(t+1)*DD + c]=Pq1;
            pqp[(t+2)*DD + c]=Pq2; pqp[(t+3)*DD + c]=Pq3;
        }

        #pragma unroll
        for (int i=0;i<4;i++){ qv[i]=nq[i]; kv[i]=nk[i]; vv[i]=nv[i]; gg[i]=ng[i]; }
        dt0=nd0; dt1=nd1; dt2=nd2; dt3=nd3;
    }
}

// ---------------------------------------------------------------------------
// Kernel 5: gate from reconstructed error. warp per token.
// ---------------------------------------------------------------------------
__global__ void __launch_bounds__(256) gate_kernel(){
    const int tid = threadIdx.x;
    const int warp = tid>>5, lane = tid&31;
    long tok = (long)blockIdx.x*8 + warp;
    float s = 0.f;
    #pragma unroll
    for (int h=0; h<2; h++){
        int c = lane + h*32;
        float v  = g_v[tok*DD + c];
        float pf = g_pqf[tok*DD + c];
        float ps = g_pqs[tok*DD + c];
        float e = v - 0.5f*(pf + ps);
        s += e*e;
    }
    const unsigned FULL = 0xffffffffu;
    #pragma unroll
    for (int d=1; d<32; d<<=1) s += __shfl_xor_sync(FULL,s,d);
    if (lane==0){
        // sigmoid(err/(1+1e-6)) > 0.7  <=>  err > ln(7/3)*(1+1e-6)
        g_gate[tok] = (s > 0.84729871f) ? 0.1f : 0.0f;
    }
}

// ---------------------------------------------------------------------------
// Kernel 6: ns scan + pw combine, unroll-8 with batched prefetch.
// ---------------------------------------------------------------------------
__global__ void __launch_bounds__(64,1) ns_kernel(){
    const int b = blockIdx.x;
    const int c = threadIdx.x;
    const long tb = (long)b*SS;
    float ns = 0.f;
    for (int tt=0; tt<SS; tt+=8){
        float gg[8], nn[8], of[8], os[8];
        float4 pw4[8];
        #pragma unroll
        for (int j=0;j<8;j++){
            long tok = tb + tt + j;
            gg[j] = g_gate[tok];
            nn[j] = g_nu[tok*DD + c];
            of[j] = g_outf[tok*DD + c];
            os[j] = g_outs[tok*DD + c];
            pw4[j] = *(const float4*)&g_pw[tok*4];
        }
        #pragma unroll
        for (int j=0;j<8;j++){
            ns = fmaf(gg[j], nn[j] - ns, ns);
            g_outpre[(tb+tt+j)*DD + c] =
                pw4[j].x*of[j] + pw4[j].y*os[j] + pw4[j].z*ns;
        }
    }
}

// ---------------------------------------------------------------------------
// Kernel 7: RMSNorm. warp per row.
// ---------------------------------------------------------------------------
__global__ void __launch_bounds__(256) rms_kernel(const float* __restrict__ norm_w){
    long row = (long)blockIdx.x*8 + (threadIdx.x>>5);
    int lane = threadIdx.x & 31;
    float x0 = g_outpre[row*DD + lane];
    float x1 = g_outpre[row*DD + 32 + lane];
    float ss = x0*x0 + x1*x1;
    #pragma unroll
    for (int d=1; d<32; d<<=1) ss += __shfl_xor_sync(0xffffffffu, ss, d);
    float inv = rsqrtf(ss*(1.0f/64.0f) + 1e-6f);
    g_a[row*DD + lane]      = x0*inv*norm_w[lane];
    g_a[row*DD + 32 + lane] = x1*inv*norm_w[32+lane];
}

// ---------------------------------------------------------------------------
// Kernel 8: out = g_a[8192,64] @ Wo[64,2048]. 64x64 tiles.
// ---------------------------------------------------------------------------
__global__ void __launch_bounds__(256,2) outgemm_kernel(
    const float* __restrict__ Wo, float* __restrict__ out)
{
    __shared__ __align__(16) float AsT[64][68];
    __shared__ __align__(16) float Bs[64][68];
    const int n0   = blockIdx.x*64;
    const int row0 = blockIdx.y*64;
    const int tid  = threadIdx.x;
    #pragma unroll
    for (int l=0;l<4;l++){
        int s = tid + l*256;
        int rr = s>>4, kq = s&15;
        float4 a4 = *(const float4*)&g_a[(long)(row0+rr)*DD + kq*4];
        AsT[kq*4+0][rr]=a4.x; AsT[kq*4+1][rr]=a4.y;
        AsT[kq*4+2][rr]=a4.z; AsT[kq*4+3][rr]=a4.w;
        float4 b4 = *(const float4*)&Wo[(long)rr*NN + n0 + kq*4];
        *(float4*)&Bs[rr][kq*4] = b4;
    }
    __syncthreads();
    const int tr = tid>>4, tc = tid&15;
    float acc[4][4];
    #pragma unroll
    for (int i=0;i<4;i++)
        #pragma unroll
        for (int j=0;j<4;j++) acc[i][j]=0.f;
    #pragma unroll 8
    for (int k=0;k<64;k++){
        float4 a4 = *(const float4*)&AsT[k][tr*4];
        float4 b4 = *(const float4*)&Bs[k][tc*4];
        float am[4]={a4.x,a4.y,a4.z,a4.w}, bn[4]={b4.x,b4.y,b4.z,b4.w};
        #pragma unroll
        for (int i=0;i<4;i++)
            #pragma unroll
            for (int j=0;j<4;j++) acc[i][j]=fmaf(am[i],bn[j],acc[i][j]);
    }
    #pragma unroll
    for (int i=0;i<4;i++){
        *(float4*)&out[(long)(row0+tr*4+i)*NN + n0 + tc*4] =
            make_float4(acc[i][0],acc[i][1],acc[i][2],acc[i][3]);
    }
}

extern "C" void kernel_launch(void* const* d_in, const int* in_sizes, int n_in,
                              void* d_out, int out_size)
{
    const float* x      = (const float*)d_in[0];
    const float* Wk     = (const float*)d_in[1];
    const float* Wv     = (const float*)d_in[2];
    const float* Wq     = (const float*)d_in[3];
    const float* fa     = (const float*)d_in[4];
    const float* sa     = (const float*)d_in[5];
    const float* nm_w1  = (const float*)d_in[6];
    const float* nm_b1  = (const float*)d_in[7];
    const float* nm_w2  = (const float*)d_in[8];
    const float* nm_b2  = (const float*)d_in[9];
    const float* ir_w1  = (const float*)d_in[10];
    const float* ir_b1  = (const float*)d_in[11];
    const float* ir_w2  = (const float*)d_in[12];
    const float* ir_b2  = (const float*)d_in[13];
    const float* pw_w   = (const float*)d_in[14];
    const float* pw_b   = (const float*)d_in[15];
    const float* Wo     = (const float*)d_in[16];
    const float* norm_w = (const float*)d_in[17];
    float* out = (float*)d_out;

    // scanFS_kernel kept at launch position 3 for the ncu -s 5 -c 1 slot.
    pw_kernel<<<128, 256>>>(x, pw_w, pw_b);
    proj_kernel<<<dim3(64,4), 256>>>(x, Wk, Wv, Wq, ir_w1, ir_b1, ir_w2, ir_b2);
    dots4_kernel<<<256, 256>>>();
    scanFS_kernel<<<dim3(8,4,2), 128>>>(fa, sa);
    nu_kernel<<<1024, 256>>>(nm_w1, nm_b1, nm_w2, nm_b2);
    gate_kernel<<<1024, 256>>>();
    ns_kernel<<<4, 64>>>();
    rms_kernel<<<1024, 256>>>(norm_w);
    outgemm_kernel<<<dim3(32,128), 256>>>(Wo, out);
}

// round 10
// speedup vs baseline: 2.2944x; 1.1203x over previous
#include <cuda_runtime.h>
#include <cuda_bf16.h>
#include <math.h>

#define BB 4
#define SS 2048
#define DD 64
#define NN 2048
#define NTOK (BB*SS)
#define CT 64                 // chunk length (tokens)
#define NCH (SS/CT)           // 32 chunks per batch
#define NCHT (BB*NCH)         // 128 chunks total

// -------- static device scratch (no allocations allowed) ----------
__device__ float g_k[NTOK*DD];
__device__ float g_q[NTOK*DD];
__device__ float g_v[NTOK*DD];
__device__ float g_nu[NTOK*DD];
__device__ float g_pw[NTOK*4];
__device__ float g_us[NTOK];
__device__ float g_outf[NTOK*DD];
__device__ float g_outs[NTOK*DD];
__device__ float g_pqf[NTOK*DD];
__device__ float g_pqs[NTOK*DD];
__device__ float g_kk[NCHT*CT*CT];      // kk[i][j] = k_i . k_j  (full)
__device__ float g_qx[NCHT*CT*CT];      // qx[i][j] = q_i . k_j  (full; diag = qk)
__device__ float g_W [2*NCHT*CT*CT];    // (I+L)^-1 per chunk-state
__device__ float g_A2[2*NCHT*CT*CT];    // a^{i-1-j} qx_ij (strict lower) per chunk-state
__device__ float g_gate[NTOK];
__device__ float g_outpre[NTOK*DD];
__device__ float g_a[NTOK*DD];

__device__ __forceinline__ float gelu_exact(float x){
    return 0.5f*x*(1.0f + erff(x*0.70710678118654752f));
}
__device__ __forceinline__ float dot4(float4 a, float4 b){
    return a.x*b.x + a.y*b.y + a.z*b.z + a.w*b.w;
}

// ---------------------------------------------------------------------------
// Kernel 1: fused projection GEMMs. grid (64 row-tiles, 4 segments), 256 thr.
// ---------------------------------------------------------------------------
__global__ void __launch_bounds__(256,2) proj_kernel(
    const float* __restrict__ x,
    const float* __restrict__ Wk, const float* __restrict__ Wv,
    const float* __restrict__ Wq, const float* __restrict__ ir_w1,
    const float* __restrict__ ir_b1, const float* __restrict__ ir_w2,
    const float* __restrict__ ir_b2)
{
    __shared__ __align__(16) float As[2][16][132];
    __shared__ __align__(16) float Bs[2][16][68];

    const int seg  = blockIdx.y;
    const int row0 = blockIdx.x * 128;
    const float* __restrict__ B = (seg==0)?Wk:(seg==1)?Wv:(seg==2)?Wq:ir_w1;

    const int tid = threadIdx.x;
    const int tr = tid >> 4;
    const int tc = tid & 15;

    float acc[8][4];
    #pragma unroll
    for (int i=0;i<8;i++)
        #pragma unroll
        for (int j=0;j<4;j++) acc[i][j]=0.f;

    float4 ra[2]; float4 rb;

    {
        #pragma unroll
        for (int j=0;j<2;j++){
            int s = tid*2 + j;
            int m = s >> 2, k4 = s & 3;
            ra[j] = *(const float4*)&x[(long)(row0+m)*NN + k4*4];
        }
        { int kk = tid >> 4, c4 = tid & 15;
          rb = *(const float4*)&B[(long)kk*DD + c4*4]; }
        #pragma unroll
        for (int j=0;j<2;j++){
            int s = tid*2+j; int m = s>>2, k4 = s&3;
            As[0][k4*4+0][m]=ra[j].x; As[0][k4*4+1][m]=ra[j].y;
            As[0][k4*4+2][m]=ra[j].z; As[0][k4*4+3][m]=ra[j].w;
        }
        { int kk=tid>>4, c4=tid&15; *(float4*)&Bs[0][kk][c4*4] = rb; }
    }
    __syncthreads();

    for (int c=0; c<128; c++){
        const int buf = c & 1;
        if (c+1 < 128){
            int k0 = (c+1)*16;
            #pragma unroll
            for (int j=0;j<2;j++){
                int s = tid*2 + j; int m = s>>2, k4 = s&3;
                ra[j] = *(const float4*)&x[(long)(row0+m)*NN + k0 + k4*4];
            }
            int kk = tid>>4, c4 = tid&15;
            rb = *(const float4*)&B[(long)(k0+kk)*DD + c4*4];
        }
        #pragma unroll
        for (int kk=0; kk<16; kk++){
            float4 a0 = *(float4*)&As[buf][kk][tr*8];
            float4 a1 = *(float4*)&As[buf][kk][tr*8+4];
            float4 bb = *(float4*)&Bs[buf][kk][tc*4];
            float am[8] = {a0.x,a0.y,a0.z,a0.w,a1.x,a1.y,a1.z,a1.w};
            float bn[4] = {bb.x,bb.y,bb.z,bb.w};
            #pragma unroll
            for (int i=0;i<8;i++)
                #pragma unroll
                for (int j=0;j<4;j++) acc[i][j] = fmaf(am[i], bn[j], acc[i][j]);
        }
        if (c+1 < 128){
            int nb = (c+1)&1;
            #pragma unroll
            for (int j=0;j<2;j++){
                int s = tid*2+j; int m=s>>2,k4=s&3;
                As[nb][k4*4+0][m]=ra[j].x; As[nb][k4*4+1][m]=ra[j].y;
                As[nb][k4*4+2][m]=ra[j].z; As[nb][k4*4+3][m]=ra[j].w;
            }
            int kk=tid>>4,c4=tid&15;
            *(float4*)&Bs[nb][kk][c4*4]=rb;
        }
        __syncthreads();
    }

    const unsigned FULL = 0xffffffffu;
    if (seg==0 || seg==2){
        float* dst = (seg==0)? g_k : g_q;
        #pragma unroll
        for (int i=0;i<8;i++){
            float s = acc[i][0]*acc[i][0]+acc[i][1]*acc[i][1]
                    + acc[i][2]*acc[i][2]+acc[i][3]*acc[i][3];
            s += __shfl_xor_sync(FULL, s, 1);
            s += __shfl_xor_sync(FULL, s, 2);
            s += __shfl_xor_sync(FULL, s, 4);
            s += __shfl_xor_sync(FULL, s, 8);
            float inv = 1.0f / fmaxf(sqrtf(s), 1e-12f);
            long row = row0 + tr*8 + i;
            *(float4*)&dst[row*DD + tc*4] =
                make_float4(acc[i][0]*inv, acc[i][1]*inv, acc[i][2]*inv, acc[i][3]*inv);
        }
    } else if (seg==1){
        #pragma unroll
        for (int i=0;i<8;i++){
            long row = row0 + tr*8 + i;
            *(float4*)&g_v[row*DD + tc*4] =
                make_float4(acc[i][0],acc[i][1],acc[i][2],acc[i][3]);
        }
    } else {
        float b1v[4], w2v[4];
        #pragma unroll
        for (int j=0;j<4;j++){ b1v[j]=ir_b1[tc*4+j]; w2v[j]=ir_w2[tc*4+j]; }
        float b2 = ir_b2[0];
        #pragma unroll
        for (int i=0;i<8;i++){
            float p = 0.f;
            #pragma unroll
            for (int j=0;j<4;j++) p += gelu_exact(acc[i][j]+b1v[j]) * w2v[j];
            p += __shfl_xor_sync(FULL, p, 1);
            p += __shfl_xor_sync(FULL, p, 2);
            p += __shfl_xor_sync(FULL, p, 4);
            p += __shfl_xor_sync(FULL, p, 8);
            if (tc==0){
                long row = row0 + tr*8 + i;
                g_us[row] = (p + b2) > 0.f ? 1.f : 0.f;
            }
        }
    }
}

// ---------------------------------------------------------------------------
// Kernel 2: per-chunk Gram matrices. block p = chunk; t0 = p*64.
// KK[i][j] = k_i.k_j, QK[i][j] = q_i.k_j. 128 blocks x 256 thr.
// ---------------------------------------------------------------------------
__global__ void __launch_bounds__(256) chunkdots_kernel(){
    __shared__ __align__(16) float Ks[CT][68];
    __shared__ __align__(16) float Qs[CT][68];
    const int p = blockIdx.x;
    const long t0 = (long)p*CT;
    const int tid = threadIdx.x;
    const float4* kp = (const float4*)(g_k + t0*DD);
    const float4* qp = (const float4*)(g_q + t0*DD);
    #pragma unroll
    for (int l=0;l<4;l++){
        int f4 = tid + l*256;
        int row = f4 >> 4, col = (f4 & 15)*4;
        *(float4*)&Ks[row][col] = kp[f4];
        *(float4*)&Qs[row][col] = qp[f4];
    }
    __syncthreads();
    #pragma unroll
    for (int m=0;m<16;m++){
        int idx = tid + m*256;
        int i = idx >> 6, j = idx & 63;
        float sk = 0.f, sq = 0.f;
        #pragma unroll
        for (int r4=0;r4<16;r4++){
            float4 kj = *(float4*)&Ks[j][r4*4];
            float4 ki = *(float4*)&Ks[i][r4*4];
            float4 qi = *(float4*)&Qs[i][r4*4];
            sk += dot4(ki,kj);
            sq += dot4(qi,kj);
        }
        g_kk[(long)p*4096 + idx] = sk;
        g_qx[(long)p*4096 + idx] = sq;
    }
}

// ---------------------------------------------------------------------------
// Kernel 3: per chunk-state: build L, invert (I+L) -> W, build A2.
// grid (128, 2), 64 threads. Thread j owns column j of W (no cross deps).
// ---------------------------------------------------------------------------
__global__ void __launch_bounds__(64) prep_kernel(
    const float* __restrict__ fa_p, const float* __restrict__ sa_p)
{
    __shared__ float L[CT][65];
    __shared__ float W[CT][65];
    __shared__ float apow[CT];
    __shared__ float gi[CT];
    const int p = blockIdx.x;
    const int st = blockIdx.y;
    const long t0 = (long)p*CT;
    const int tid = threadIdx.x;
    const float a = st ? *sa_p : *fa_p;
    const float oa = 1.0f - a;
    if (tid == 0){
        float w = 1.f;
        for (int i=0;i<CT;i++){ apow[i] = w; w *= a; }
    }
    gi[tid] = st ? oa*g_us[t0+tid] : oa;
    __syncthreads();
    const long base = (long)p*4096;
    const long obase = ((long)st*NCHT + p)*4096;
    for (int f = tid; f < 4096; f += 64){
        int i = f >> 6, j = f & 63;
        float dec = (j < i) ? apow[i-1-j] : 0.f;
        L[i][j] = dec * gi[i] * g_kk[base+f];
        g_A2[obase+f] = dec * g_qx[base+f];
    }
    __syncthreads();
    // forward substitution, column tid
    {
        const int j = tid;
        for (int i=0;i<CT;i++) W[i][j] = (i==j) ? 1.f : 0.f;
        for (int i=j+1;i<CT;i++){
            float s = 0.f;
            for (int k=j;k<i;k++) s = fmaf(L[i][k], W[k][j], s);
            W[i][j] = -s;
        }
    }
    __syncthreads();
    for (int f = tid; f < 4096; f += 64)
        g_W[obase+f] = W[f>>6][f&63];
}

// ---------------------------------------------------------------------------
// Kernel 4: chunked scan. grid (16 colgroups, 4 batches, 2 states), 256 thr.
// Each block owns 4 columns of H; serial only over the 32 chunks.
// Per chunk: KH/QH GEMMs, rhs, C = W@rhs, Pq = diag(a^i)QH + A2@C,
// out = a*Pq + qk*c, H <- a^64 H + K^T diag(a^{63-j}) C.
// ---------------------------------------------------------------------------
__global__ void __launch_bounds__(256,1) scan_chunk_kernel(
    const float* __restrict__ fa_p, const float* __restrict__ sa_p)
{
    __shared__ __align__(16) float Ks[CT][68];
    __shared__ __align__(16) float Ss[CT][68];   // staging: Q -> W -> A2
    __shared__ __align__(16) float H [4][68];
    __shared__ __align__(16) float T1[4][68];    // rhs -> CS
    __shared__ __align__(16) float Cc[4][68];
    __shared__ __align__(16) float QHs[4][68];
    __shared__ float apow[CT];

    const int cg = blockIdx.x;       // column group (4 cols)
    const int b  = blockIdx.y;
    const int st = blockIdx.z;
    const int tid = threadIdx.x;
    const int i = tid >> 2;          // row/token within chunk
    const int c = tid & 3;           // local column
    const int colg = cg*4 + c;
    const float a = st ? *sa_p : *fa_p;
    const float oa = 1.0f - a;
    float* __restrict__ outp = st ? g_outs : g_outf;
    float* __restrict__ pqp  = st ? g_pqs  : g_pqf;

    if (tid == 0){
        float w = 1.f;
        for (int t=0;t<CT;t++){ apow[t] = w; w *= a; }
    }
    H[c][i] = 0.f;
    __syncthreads();
    const float a64 = apow[63]*a;

    for (int ch = 0; ch < NCH; ch++){
        const int  pidx = b*NCH + ch;
        const long t0   = (long)pidx*CT;
        const long wbase = ((long)st*NCHT + pidx)*4096;

        // stage K and Q (coalesced float4)
        {
            const float4* kp = (const float4*)(g_k + t0*DD);
            const float4* qp = (const float4*)(g_q + t0*DD);
            #pragma unroll
            for (int l=0;l<4;l++){
                int f4 = tid + l*256;
                int row = f4 >> 4, col = (f4 & 15)*4;
                *(float4*)&Ks[row][col] = kp[f4];
                *(float4*)&Ss[row][col] = qp[f4];
            }
        }
        __syncthreads();

        // KH and QH against chunk-entry H, then rhs
        {
            float akh = 0.f, aqh = 0.f;
            #pragma unroll
            for (int r4=0;r4<16;r4++){
                float4 h4 = *(float4*)&H [c][r4*4];
                float4 k4 = *(float4*)&Ks[i][r4*4];
                float4 q4 = *(float4*)&Ss[i][r4*4];
                akh += dot4(k4,h4);
                aqh += dot4(q4,h4);
            }
            float giv = st ? oa*g_us[t0+i] : oa;
            float v   = g_v[(t0+i)*DD + colg];
            T1[c][i]  = giv*(v - apow[i]*akh);
            QHs[c][i] = aqh;
        }
        __syncthreads();

        // stage W
        {
            const float4* wp = (const float4*)(g_W + wbase);
            #pragma unroll
            for (int l=0;l<4;l++){
                int f4 = tid + l*256;
                int row = f4 >> 4, col = (f4 & 15)*4;
                *(float4*)&Ss[row][col] = wp[f4];
            }
        }
        __syncthreads();

        // C = W @ rhs
        {
            float s = 0.f;
            #pragma unroll
            for (int j4=0;j4<16;j4++){
                float4 w4 = *(float4*)&Ss[i][j4*4];
                float4 r4 = *(float4*)&T1[c][j4*4];
                s += dot4(w4,r4);
            }
            Cc[c][i] = s;
        }
        __syncthreads();

        // stage A2
        {
            const float4* ap = (const float4*)(g_A2 + wbase);
            #pragma unroll
            for (int l=0;l<4;l++){
                int f4 = tid + l*256;
                int row = f4 >> 4, col = (f4 & 15)*4;
                *(float4*)&Ss[row][col] = ap[f4];
            }
        }
        __syncthreads();

        // Pq, out; CS into T1
        {
            float s = 0.f;
            #pragma unroll
            for (int j4=0;j4<16;j4++){
                float4 a4 = *(float4*)&Ss[i][j4*4];
                float4 c4 = *(float4*)&Cc[c][j4*4];
                s += dot4(a4,c4);
            }
            float ci = Cc[c][i];
            float pq = fmaf(apow[i], QHs[c][i], s);
            float qk = g_qx[(long)pidx*4096 + i*65];
            float o  = fmaf(qk, ci, a*pq);
            pqp [(t0+i)*DD + colg] = pq;
            outp[(t0+i)*DD + colg] = o;
            T1[c][i] = apow[63-i]*ci;   // CS
        }
        __syncthreads();

        // H <- a^64 H + K^T CS
        {
            float h = a64*H[c][i];
            #pragma unroll
            for (int j=0;j<CT;j++)
                h = fmaf(Ks[j][i], T1[c][j], h);
            H[c][i] = h;
        }
        __syncthreads();
    }
}

// ---------------------------------------------------------------------------
// Kernel 5: pw = softmax(x @ pw_w + pw_b). warp per token.
// ---------------------------------------------------------------------------
__global__ void __launch_bounds__(256) pw_kernel(
    const float* __restrict__ x, const float* __restrict__ pw_w,
    const float* __restrict__ pw_b)
{
    __shared__ __align__(16) float pwT[3][2048];
    const int tid = threadIdx.x;
    for (int idx = tid; idx < 3*2048; idx += 256){
        int i = idx/3, cc = idx - i*3;
        pwT[cc][i] = pw_w[idx];
    }
    __syncthreads();
    const int warp = tid>>5, lane = tid&31;
    const float b0 = pw_b[0], b1 = pw_b[1], b2 = pw_b[2];
    const unsigned FULL = 0xffffffffu;
    for (int it8 = 0; it8 < 8; it8++){
        long tok = (long)blockIdx.x*64 + warp*8 + it8;
        const float* xr = x + tok*NN;
        float a0=0.f,a1=0.f,a2=0.f;
        #pragma unroll
        for (int it=0; it<16; it++){
            int off = it*128 + lane*4;
            float4 xv = *(const float4*)&xr[off];
            float4 w0 = *(const float4*)&pwT[0][off];
            float4 w1 = *(const float4*)&pwT[1][off];
            float4 w2 = *(const float4*)&pwT[2][off];
            a0 += dot4(xv,w0);
            a1 += dot4(xv,w1);
            a2 += dot4(xv,w2);
        }
        #pragma unroll
        for (int d=1; d<32; d<<=1){
            a0 += __shfl_xor_sync(FULL, a0, d);
            a1 += __shfl_xor_sync(FULL, a1, d);
            a2 += __shfl_xor_sync(FULL, a2, d);
        }
        if (lane==0){
            float l0=a0+b0, l1=a1+b1, l2=a2+b2;
            float m = fmaxf(l0, fmaxf(l1,l2));
            float e0=expf(l0-m), e1=expf(l1-m), e2=expf(l2-m);
            float inv = 1.0f/(e0+e1+e2);
            g_pw[tok*4+0]=e0*inv; g_pw[tok*4+1]=e1*inv;
            g_pw[tok*4+2]=e2*inv; g_pw[tok*4+3]=0.f;
        }
    }
}

// ---------------------------------------------------------------------------
// Kernel 6: nu = gelu(v @ nm_w1 + b1) @ nm_w2 + b2. warp per token.
// ---------------------------------------------------------------------------
__global__ void __launch_bounds__(256) nu_kernel(
    const float* __restrict__ nm_w1, const float* __restrict__ nm_b1,
    const float* __restrict__ nm_w2, const float* __restrict__ nm_b2)
{
    __shared__ float W1s[64*128];
    __shared__ float hs[8][128];
    __shared__ float vs[8][64];
    const int tid = threadIdx.x;
    for (int i = tid; i < 64*128; i += 256) W1s[i] = nm_w1[i];
    long tok0 = (long)blockIdx.x*8;
    for (int i = tid; i < 8*64; i += 256){
        int t = i>>6, r = i&63;
        vs[t][r] = g_v[(tok0+t)*DD + r];
    }
    __syncthreads();
    const int warp = tid>>5, lane = tid&31;
    #pragma unroll
    for (int ii=0;ii<4;ii++){
        int i = lane + ii*32;
        float a = nm_b1[i];
        #pragma unroll 8
        for (int r=0;r<64;r++) a = fmaf(vs[warp][r], W1s[r*128+i], a);
        hs[warp][i] = gelu_exact(a);
    }
    __syncwarp();
    #pragma unroll
    for (int jj=0;jj<2;jj++){
        int j = lane + jj*32;
        float a = nm_b2[j];
        #pragma unroll 8
        for (int i=0;i<128;i++) a = fmaf(hs[warp][i], __ldg(&nm_w2[i*64+j]), a);
        g_nu[(tok0+warp)*DD + j] = a;
    }
}

// ---------------------------------------------------------------------------
// Kernel 7: gate from reconstructed error. warp per token.
// ---------------------------------------------------------------------------
__global__ void __launch_bounds__(256) gate_kernel(){
    const int tid = threadIdx.x;
    const int warp = tid>>5, lane = tid&31;
    long tok = (long)blockIdx.x*8 + warp;
    float s = 0.f;
    #pragma unroll
    for (int h=0; h<2; h++){
        int c = lane + h*32;
        float v  = g_v[tok*DD + c];
        float pf = g_pqf[tok*DD + c];
        float ps = g_pqs[tok*DD + c];
        float e = v - 0.5f*(pf + ps);
        s += e*e;
    }
    const unsigned FULL = 0xffffffffu;
    #pragma unroll
    for (int d=1; d<32; d<<=1) s += __shfl_xor_sync(FULL,s,d);
    if (lane==0){
        // sigmoid(err/(1+1e-6)) > 0.7  <=>  err > ln(7/3)*(1+1e-6)
        g_gate[tok] = (s > 0.84729871f) ? 0.1f : 0.0f;
    }
}

// ---------------------------------------------------------------------------
// Kernel 8: ns scan + pw combine, unroll-8 with batched prefetch.
// ---------------------------------------------------------------------------
__global__ void __launch_bounds__(64,1) ns_kernel(){
    const int b = blockIdx.x;
    const int c = threadIdx.x;
    const long tb = (long)b*SS;
    float ns = 0.f;
    for (int tt=0; tt<SS; tt+=8){
        float gg[8], nn[8], of[8], os[8];
        float4 pw4[8];
        #pragma unroll
        for (int j=0;j<8;j++){
            long tok = tb + tt + j;
            gg[j] = g_gate[tok];
            nn[j] = g_nu[tok*DD + c];
            of[j] = g_outf[tok*DD + c];
            os[j] = g_outs[tok*DD + c];
            pw4[j] = *(const float4*)&g_pw[tok*4];
        }
        #pragma unroll
        for (int j=0;j<8;j++){
            ns = fmaf(gg[j], nn[j] - ns, ns);
            g_outpre[(tb+tt+j)*DD + c] =
                pw4[j].x*of[j] + pw4[j].y*os[j] + pw4[j].z*ns;
        }
    }
}

// ---------------------------------------------------------------------------
// Kernel 9: RMSNorm. warp per row.
// ---------------------------------------------------------------------------
__global__ void __launch_bounds__(256) rms_kernel(const float* __restrict__ norm_w){
    long row = (long)blockIdx.x*8 + (threadIdx.x>>5);
    int lane = threadIdx.x & 31;
    float x0 = g_outpre[row*DD + lane];
    float x1 = g_outpre[row*DD + 32 + lane];
    float ss = x0*x0 + x1*x1;
    #pragma unroll
    for (int d=1; d<32; d<<=1) ss += __shfl_xor_sync(0xffffffffu, ss, d);
    float inv = rsqrtf(ss*(1.0f/64.0f) + 1e-6f);
    g_a[row*DD + lane]      = x0*inv*norm_w[lane];
    g_a[row*DD + 32 + lane] = x1*inv*norm_w[32+lane];
}

// ---------------------------------------------------------------------------
// Kernel 10: out = g_a[8192,64] @ Wo[64,2048]. 64x64 tiles.
// ---------------------------------------------------------------------------
__global__ void __launch_bounds__(256,2) outgemm_kernel(
    const float* __restrict__ Wo, float* __restrict__ out)
{
    __shared__ __align__(16) float AsT[64][68];
    __shared__ __align__(16) float Bs[64][68];
    const int n0   = blockIdx.x*64;
    const int row0 = blockIdx.y*64;
    const int tid  = threadIdx.x;
    #pragma unroll
    for (int l=0;l<4;l++){
        int s = tid + l*256;
        int rr = s>>4, kq = s&15;
        float4 a4 = *(const float4*)&g_a[(long)(row0+rr)*DD + kq*4];
        AsT[kq*4+0][rr]=a4.x; AsT[kq*4+1][rr]=a4.y;
        AsT[kq*4+2][rr]=a4.z; AsT[kq*4+3][rr]=a4.w;
        float4 b4 = *(const float4*)&Wo[(long)rr*NN + n0 + kq*4];
        *(float4*)&Bs[rr][kq*4] = b4;
    }
    __syncthreads();
    const int tr = tid>>4, tc = tid&15;
    float acc[4][4];
    #pragma unroll
    for (int i=0;i<4;i++)
        #pragma unroll
        for (int j=0;j<4;j++) acc[i][j]=0.f;
    #pragma unroll 8
    for (int k=0;k<64;k++){
        float4 a4 = *(const float4*)&AsT[k][tr*4];
        float4 b4 = *(const float4*)&Bs[k][tc*4];
        float am[4]={a4.x,a4.y,a4.z,a4.w}, bn[4]={b4.x,b4.y,b4.z,b4.w};
        #pragma unroll
        for (int i=0;i<4;i++)
            #pragma unroll
            for (int j=0;j<4;j++) acc[i][j]=fmaf(am[i],bn[j],acc[i][j]);
    }
    #pragma unroll
    for (int i=0;i<4;i++){
        *(float4*)&out[(long)(row0+tr*4+i)*NN + n0 + tc*4] =
            make_float4(acc[i][0],acc[i][1],acc[i][2],acc[i][3]);
    }
}

extern "C" void kernel_launch(void* const* d_in, const int* in_sizes, int n_in,
                              void* d_out, int out_size)
{
    const float* x      = (const float*)d_in[0];
    const float* Wk     = (const float*)d_in[1];
    const float* Wv     = (const float*)d_in[2];
    const float* Wq     = (const float*)d_in[3];
    const float* fa     = (const float*)d_in[4];
    const float* sa     = (const float*)d_in[5];
    const float* nm_w1  = (const float*)d_in[6];
    const float* nm_b1  = (const float*)d_in[7];
    const float* nm_w2  = (const float*)d_in[8];
    const float* nm_b2  = (const float*)d_in[9];
    const float* ir_w1  = (const float*)d_in[10];
    const float* ir_b1  = (const float*)d_in[11];
    const float* ir_w2  = (const float*)d_in[12];
    const float* ir_b2  = (const float*)d_in[13];
    const float* pw_w   = (const float*)d_in[14];
    const float* pw_b   = (const float*)d_in[15];
    const float* Wo     = (const float*)d_in[16];
    const float* norm_w = (const float*)d_in[17];
    float* out = (float*)d_out;

    // scan_chunk_kernel kept at launch position 4 for the ncu capture slot.
    proj_kernel<<<dim3(64,4), 256>>>(x, Wk, Wv, Wq, ir_w1, ir_b1, ir_w2, ir_b2);
    chunkdots_kernel<<<NCHT, 256>>>();
    prep_kernel<<<dim3(NCHT,2), 64>>>(fa, sa);
    scan_chunk_kernel<<<dim3(16,BB,2), 256>>>(fa, sa);
    pw_kernel<<<128, 256>>>(x, pw_w, pw_b);
    nu_kernel<<<1024, 256>>>(nm_w1, nm_b1, nm_w2, nm_b2);
    gate_kernel<<<1024, 256>>>();
    ns_kernel<<<4, 64>>>();
    rms_kernel<<<1024, 256>>>(norm_w);
    outgemm_kernel<<<dim3(32,128), 256>>>(Wo, out);
}